// round 7
// baseline (speedup 1.0000x reference)
#include <cuda_runtime.h>
#include <cuda_bf16.h>
#include <math.h>

#define BDIM 2
#define NSEQ 2048
#define LDIM 1024
#define DDIM 1024
#define HH   16
#define HDM  64
#define BNROWS (BDIM*NSEQ)   // 4096
#define SM_SCALE 0.125f

static const long OUT1   = (long)BDIM * NSEQ * DDIM;        // 4,194,304
static const long AELEMS = (long)BDIM * HH * NSEQ * NSEQ;   // 134,217,728

typedef __nv_bfloat16 bf16;
typedef __nv_bfloat162 bf162;

// ---------------- device scratch (no cudaMalloc anywhere) ----------------
__device__ __align__(256) bf16 g_xh[BNROWS*LDIM], g_xl[BNROWS*LDIM];
__device__ __align__(256) bf16 g_wh[5][LDIM*DDIM], g_wl[5][LDIM*DDIM];
__device__ __align__(256) bf16 g_Qh[BNROWS*DDIM], g_Ql[BNROWS*DDIM];
__device__ __align__(256) bf16 g_Kh[BNROWS*DDIM], g_Kl[BNROWS*DDIM];
__device__ float g_V[BNROWS*DDIM];
__device__ float g_G[BNROWS*DDIM];
__device__ __align__(256) bf16 g_VGh[BNROWS*DDIM];
__device__ __align__(256) bf16 g_Mh[BNROWS*DDIM];
__device__ float g_Y[BNROWS*DDIM];
__device__ float g_L[(long)BDIM*HH*NSEQ];                  // softmax row sums
__device__ float g_Afb[(size_t)BDIM*HH*NSEQ*NSEQ];  // fallback if A not in output

// ---------------- PTX helpers ----------------
__device__ __forceinline__ unsigned smem_u32(const void* p) {
    return (unsigned)__cvta_generic_to_shared(p);
}
__device__ __forceinline__ void cp16(unsigned dst, const void* src) {
    asm volatile("cp.async.ca.shared.global [%0], [%1], 16;\n" :: "r"(dst), "l"(src));
}
__device__ __forceinline__ void cp_commit() { asm volatile("cp.async.commit_group;\n" ::); }
template<int N> __device__ __forceinline__ void cp_wait() {
    asm volatile("cp.async.wait_group %0;\n" :: "n"(N));
}
__device__ __forceinline__ void ldm_x4(unsigned* d, unsigned addr) {
    asm volatile("ldmatrix.sync.aligned.m8n8.x4.shared.b16 {%0,%1,%2,%3}, [%4];"
                 : "=r"(d[0]), "=r"(d[1]), "=r"(d[2]), "=r"(d[3]) : "r"(addr));
}
__device__ __forceinline__ void ldm_x4t(unsigned* d, unsigned addr) {
    asm volatile("ldmatrix.sync.aligned.m8n8.x4.trans.shared.b16 {%0,%1,%2,%3}, [%4];"
                 : "=r"(d[0]), "=r"(d[1]), "=r"(d[2]), "=r"(d[3]) : "r"(addr));
}
__device__ __forceinline__ void mma_bf16(float* c, const unsigned* a, const unsigned* b) {
    asm volatile(
        "mma.sync.aligned.m16n8k16.row.col.f32.bf16.bf16.f32 "
        "{%0,%1,%2,%3},{%4,%5,%6,%7},{%8,%9},{%0,%1,%2,%3};"
        : "+f"(c[0]), "+f"(c[1]), "+f"(c[2]), "+f"(c[3])
        : "r"(a[0]), "r"(a[1]), "r"(a[2]), "r"(a[3]), "r"(b[0]), "r"(b[1]));
}
__device__ __forceinline__ void split_bf16(float v, bf16& h, bf16& l) {
    h = __float2bfloat16_rn(v);
    l = __float2bfloat16_rn(v - __bfloat162float(h));
}
__device__ __forceinline__ unsigned pack2(float a, float b) {
    bf162 t; t.x = __float2bfloat16_rn(a); t.y = __float2bfloat16_rn(b);
    return *(unsigned*)&t;
}

// ---------------------------------------------------------------------------
// GEMM body: bf16 tensor-core GEMM, cp.async 2-stage pipeline.
// full=true -> bf16x3 error-compensated (hi/lo). full=false -> hi-only.
// ---------------------------------------------------------------------------
template<int BM, int BN, int BK, int WM, int WN, int THREADS>
__device__ __forceinline__ void gemm_body(
    int K, bool full,
    const bf16* __restrict__ Agh, const bf16* __restrict__ Agl, int lda,
    const bf16* __restrict__ Bgh, const bf16* __restrict__ Bgl, int ldb,
    float* Cf, bf16* Ch, bf16* Cl, int ldc,
    const float* bias, const float* resid, int ldr,
    float alpha, int act)
{
    constexpr int APITCH = BK + 8;
    constexpr int BPITCH = BN + 8;
    constexpr int ABYTES = BM * APITCH * 2;
    constexpr int BBYTES = BK * BPITCH * 2;
    constexpr int STAGE  = 2 * ABYTES + 2 * BBYTES;
    constexpr int MI = WM / 16, NJ = WN / 8;

    extern __shared__ char dsm[];

    const int tid  = threadIdx.x;
    const int lane = tid & 31;
    const int warp = tid >> 5;
    const int wm = warp % (BM/WM);
    const int wn = warp / (BM/WM);
    const int m0 = wm * WM, n0 = wn * WN;
    const int rowBase = blockIdx.y * BM;
    const int colBase = blockIdx.x * BN;
    const int lrow  = lane & 15;
    const int lkoff = (lane >> 4) << 3;

    float acc[MI][NJ][4];
#pragma unroll
    for (int i = 0; i < MI; i++)
#pragma unroll
        for (int j = 0; j < NJ; j++)
#pragma unroll
            for (int q = 0; q < 4; q++) acc[i][j][q] = 0.f;

    auto load_stage = [&](int s, int k0) {
        char* base = dsm + s * STAGE;
        bf16* Ash = (bf16*)(base);
        bf16* Asl = (bf16*)(base + ABYTES);
        bf16* Bsh = (bf16*)(base + 2*ABYTES);
        bf16* Bsl = (bf16*)(base + 2*ABYTES + BBYTES);
        constexpr int ACH = BM * BK / 8;
#pragma unroll
        for (int t = 0; t < ACH; t += THREADS) {
            int idx = t + tid;
            int r = idx / (BK/8);
            int c = (idx % (BK/8)) * 8;
            long so = (long)(rowBase + r) * lda + k0 + c;
            cp16(smem_u32(Ash + r*APITCH + c), Agh + so);
            if (full) cp16(smem_u32(Asl + r*APITCH + c), Agl + so);
        }
        constexpr int BCH = BK * BN / 8;
#pragma unroll
        for (int t = 0; t < BCH; t += THREADS) {
            int idx = t + tid;
            int r = idx / (BN/8);
            int c = (idx % (BN/8)) * 8;
            long so = (long)(k0 + r) * ldb + colBase + c;
            cp16(smem_u32(Bsh + r*BPITCH + c), Bgh + so);
            if (full) cp16(smem_u32(Bsl + r*BPITCH + c), Bgl + so);
        }
    };

    auto compute_stage = [&](int s) {
        char* base = dsm + s * STAGE;
        bf16* Ash = (bf16*)(base);
        bf16* Asl = (bf16*)(base + ABYTES);
        bf16* Bsh = (bf16*)(base + 2*ABYTES);
        bf16* Bsl = (bf16*)(base + 2*ABYTES + BBYTES);
#pragma unroll
        for (int kk = 0; kk < BK; kk += 16) {
            unsigned afh[MI][4], afl[MI][4];
            unsigned bfh[NJ][2], bfl[NJ][2];
#pragma unroll
            for (int mi = 0; mi < MI; mi++) {
                ldm_x4(afh[mi], smem_u32(Ash + (m0 + mi*16 + lrow)*APITCH + kk + lkoff));
                if (full) ldm_x4(afl[mi], smem_u32(Asl + (m0 + mi*16 + lrow)*APITCH + kk + lkoff));
            }
#pragma unroll
            for (int nj = 0; nj < NJ; nj += 2) {
                ldm_x4t(&bfh[nj][0], smem_u32(Bsh + (kk + lrow)*BPITCH + n0 + (nj + (lane>>4))*8));
                if (full) ldm_x4t(&bfl[nj][0], smem_u32(Bsl + (kk + lrow)*BPITCH + n0 + (nj + (lane>>4))*8));
            }
#pragma unroll
            for (int mi = 0; mi < MI; mi++)
#pragma unroll
                for (int nj = 0; nj < NJ; nj++) {
                    mma_bf16(acc[mi][nj], afh[mi], bfh[nj]);
                    if (full) {
                        mma_bf16(acc[mi][nj], afh[mi], bfl[nj]);
                        mma_bf16(acc[mi][nj], afl[mi], bfh[nj]);
                    }
                }
        }
    };

    const int KT = K / BK;
    load_stage(0, 0);
    cp_commit();
    for (int kt = 0; kt < KT; kt++) {
        if (kt + 1 < KT) {
            load_stage((kt + 1) & 1, (kt + 1) * BK);
            cp_commit();
            cp_wait<1>();
        } else {
            cp_wait<0>();
        }
        __syncthreads();
        compute_stage(kt & 1);
        __syncthreads();
    }

    // ---- epilogue ----
#pragma unroll
    for (int mi = 0; mi < MI; mi++) {
#pragma unroll
        for (int nj = 0; nj < NJ; nj++) {
            int c = colBase + n0 + nj*8 + 2*(lane & 3);
            float b0 = 0.f, b1 = 0.f;
            if (bias) { b0 = bias[c]; b1 = bias[c+1]; }
#pragma unroll
            for (int half = 0; half < 2; half++) {
                int r = rowBase + m0 + mi*16 + (lane >> 2) + half*8;
                float v0 = acc[mi][nj][half*2+0] * alpha + b0;
                float v1 = acc[mi][nj][half*2+1] * alpha + b1;
                if (act == 1) {
                    v0 = 1.f / (1.f + __expf(-v0));
                    v1 = 1.f / (1.f + __expf(-v1));
                }
                if (resid) {
                    v0 += resid[(long)r * ldr + c];
                    v1 += resid[(long)r * ldr + c + 1];
                }
                long off = (long)r * ldc + c;
                if (Cf) {
                    float2 o; o.x = v0; o.y = v1;
                    *(float2*)&Cf[off] = o;
                }
                if (Ch) {
                    bf16 h0, l0, h1, l1;
                    split_bf16(v0, h0, l0);
                    split_bf16(v1, h1, l1);
                    bf162 ph; ph.x = h0; ph.y = h1;
                    bf162 pl; pl.x = l0; pl.y = l1;
                    *(bf162*)&Ch[off] = ph;
                    *(bf162*)&Cl[off] = pl;
                }
            }
        }
    }
}

// multiplexed 4-projection kernel
struct Ptrs4 {
    const bf16* Bh[4]; const bf16* Bl[4];
    const float* bias[4];
    float* Cf[4]; bf16* Ch[4]; bf16* Cl[4];
    int act[4]; int full[4];
};

template<int BM, int BN, int BK, int WM, int WN>
__global__ __launch_bounds__((BM/WM)*(BN/WN)*32, 2)
void gemm4_kernel(int K, const bf16* __restrict__ Ah, const bf16* __restrict__ Al,
                  int lda, int ldb, int ldc, Ptrs4 p)
{
    int z = blockIdx.z;
    gemm_body<BM,BN,BK,WM,WN,(BM/WM)*(BN/WN)*32>(
        K, p.full[z] != 0, Ah, Al, lda, p.Bh[z], p.Bl[z], ldb,
        p.Cf[z], p.Ch[z], p.Cl[z], ldc,
        p.bias[z], nullptr, 0, 1.f, p.act[z]);
}

// out-projection GEMM (z==0 blocks) fused with A-row normalization (z==1 blocks).
// Norm part: 256 blocks x 256 rows; each row: A[row,:] *= 1/L[row].
template<int BM, int BN, int BK, int WM, int WN>
__global__ __launch_bounds__((BM/WM)*(BN/WN)*32, 2)
void gemm1norm_kernel(int K, int full,
                      const bf16* __restrict__ Ah, const bf16* __restrict__ Al, int lda,
                      const bf16* __restrict__ Bh, const bf16* __restrict__ Bl, int ldb,
                      float* Cf, int ldc,
                      const float* bias, const float* resid, int ldr,
                      float* __restrict__ An, const float* __restrict__ Ln)
{
    if (blockIdx.z == 0) {
        gemm_body<BM,BN,BK,WM,WN,(BM/WM)*(BN/WN)*32>(
            K, full != 0, Ah, Al, lda, Bh, Bl, ldb,
            Cf, nullptr, nullptr, ldc, bias, resid, ldr, 1.f, 0);
        return;
    }
    // normalization blocks: gridDim.x * gridDim.y blocks total
    int nb = blockIdx.y * gridDim.x + blockIdx.x;
    int nblocks = gridDim.x * gridDim.y;
    long rows_total = (long)BDIM * HH * NSEQ;          // 65536
    long rows_per = rows_total / nblocks;              // 256 for 256 blocks
    long row0 = (long)nb * rows_per;
    for (long r = 0; r < rows_per; r++) {
        long row = row0 + r;
        float inv = 1.f / Ln[row];
        float4* p = (float4*)(An + row * (long)NSEQ);
#pragma unroll
        for (int it = 0; it < 2; it++) {
            int idx = threadIdx.x + it * 256;
            float4 v = p[idx];
            v.x *= inv; v.y *= inv; v.z *= inv; v.w *= inv;
            p[idx] = v;
        }
    }
}

constexpr int stage_bytes_h(int BM, int BN, int BK) {
    return 2 * (BM * (BK + 8) * 2) + 2 * (BK * (BN + 8) * 2);
}

// ---------------------------------------------------------------------------
// Fused single-pass attention (see round-6 comments).
// ---------------------------------------------------------------------------
#define QP 72  // smem pitch (elems) for 64-wide tiles

__global__ __launch_bounds__(256, 2)
void attn_kernel(const bf16* __restrict__ Qhg, const bf16* __restrict__ Qlg,
                 const bf16* __restrict__ Khg, const bf16* __restrict__ Klg,
                 const bf16* __restrict__ Vhg,
                 float* __restrict__ Ag, float* __restrict__ Lg,
                 bf16* __restrict__ Mhg)
{
    extern __shared__ char sm[];
    const int tid = threadIdx.x, lane = tid & 31, warp = tid >> 5;
    const int bh = blockIdx.y, bb = bh >> 4, hh = bh & 15;
    const int q0 = blockIdx.x * 128;
    const long qrow = (long)bb * NSEQ + q0;
    const bf16* Qh = Qhg + qrow * DDIM + hh * HDM;
    const bf16* Ql = Qlg + qrow * DDIM + hh * HDM;
    const bf16* Kh = Khg + (long)bb * NSEQ * DDIM + hh * HDM;
    const bf16* Kl = Klg + (long)bb * NSEQ * DDIM + hh * HDM;
    const bf16* Vh = Vhg + (long)bb * NSEQ * DDIM + hh * HDM;
    float* Arow = Ag + ((long)bh * NSEQ + q0) * NSEQ;

    bf16* Qs = (bf16*)sm;
    const int lrow = lane & 15, lk = (lane >> 4) * 8;

    auto loadQ = [&]() {
        for (int t = tid; t < 2048; t += 256) {
            int hl = t >> 10, rem = t & 1023, r = rem >> 3, c = (rem & 7) * 8;
            const bf16* s = (hl ? Ql : Qh) + (long)r * DDIM + c;
            cp16(smem_u32(Qs + hl * 128 * QP + r * QP + c), s);
        }
    };
    auto loadKtile = [&](char* dst, int key0) {
        for (int t = tid; t < 2048; t += 256) {
            int hl = t >> 10, rem = t & 1023, r = rem >> 3, c = (rem & 7) * 8;
            const bf16* s = (hl ? Kl : Kh) + (long)(key0 + r) * DDIM + c;
            cp16(smem_u32((bf16*)dst + hl * 128 * QP + r * QP + c), s);
        }
    };
    auto loadVtile = [&](char* dst, int key0) {
        for (int t = tid; t < 1024; t += 256) {
            int r = t >> 3, c = (t & 7) * 8;
            cp16(smem_u32((bf16*)dst + r * QP + c), Vh + (long)(key0 + r) * DDIM + c);
        }
    };

    // ---- prologue ----
    loadQ();
    loadKtile(sm + 55296, 0);
    loadVtile(sm + 55296 + 36864, 0);
    cp_commit(); cp_wait<0>(); __syncthreads();

    unsigned aqh[4][4], aql[4][4];
#pragma unroll
    for (int kk = 0; kk < 4; kk++) {
        ldm_x4(aqh[kk], smem_u32(Qs + (warp*16 + lrow)*QP + kk*16 + lk));
        ldm_x4(aql[kk], smem_u32(Qs + 128*QP + (warp*16 + lrow)*QP + kk*16 + lk));
    }
    __syncthreads();   // Q smem free; stage0 may now overwrite it

    auto computeS = [&](const char* kb, int kg, float (&c)[2][4]) {
        const bf16* Ksh = (const bf16*)kb;
        const bf16* Ksl = Ksh + 128 * QP;
#pragma unroll
        for (int kk = 0; kk < 4; kk++) {
            unsigned rh[4], rl[4];
            ldm_x4(rh, smem_u32(Ksh + (kg*16 + lrow)*QP + kk*16 + lk));
            ldm_x4(rl, smem_u32(Ksl + (kg*16 + lrow)*QP + kk*16 + lk));
            unsigned b0h[2] = {rh[0], rh[2]}, b1h[2] = {rh[1], rh[3]};
            unsigned b0l[2] = {rl[0], rl[2]}, b1l[2] = {rl[1], rl[3]};
            mma_bf16(c[0], aqh[kk], b0h);
            mma_bf16(c[0], aqh[kk], b0l);
            mma_bf16(c[0], aql[kk], b0h);
            mma_bf16(c[1], aqh[kk], b1h);
            mma_bf16(c[1], aqh[kk], b1l);
            mma_bf16(c[1], aql[kk], b1h);
        }
    };

    float Macc[8][4] = {};
    float lsum0 = 0.f, lsum1 = 0.f;

    for (int kt = 0; kt < 16; kt++) {
        char* stg = sm + ((kt + 1) & 1) * 55296;
        if (kt < 15) {
            char* pre = sm + (kt & 1) * 55296;
            loadKtile(pre, (kt + 1) * 128);
            loadVtile(pre + 36864, (kt + 1) * 128);
            cp_commit();
        }
        const bf16* Vs = (const bf16*)(stg + 36864);
#pragma unroll 1
        for (int kg = 0; kg < 8; kg++) {
            float c[2][4] = {};
            computeS(stg, kg, c);
            float p[2][4];
#pragma unroll
            for (int nj = 0; nj < 2; nj++) {
                p[nj][0] = __expf(c[nj][0] * SM_SCALE);
                p[nj][1] = __expf(c[nj][1] * SM_SCALE);
                p[nj][2] = __expf(c[nj][2] * SM_SCALE);
                p[nj][3] = __expf(c[nj][3] * SM_SCALE);
            }
            lsum0 += p[0][0] + p[0][1] + p[1][0] + p[1][1];
            lsum1 += p[0][2] + p[0][3] + p[1][2] + p[1][3];
            long colb = (long)kt * 128 + kg * 16 + 2 * (lane & 3);
            long r0 = warp * 16 + (lane >> 2);
            float2 w;
            w.x = p[0][0]; w.y = p[0][1]; *(float2*)&Arow[r0*NSEQ + colb]           = w;
            w.x = p[1][0]; w.y = p[1][1]; *(float2*)&Arow[r0*NSEQ + colb + 8]       = w;
            w.x = p[0][2]; w.y = p[0][3]; *(float2*)&Arow[(r0+8)*NSEQ + colb]       = w;
            w.x = p[1][2]; w.y = p[1][3]; *(float2*)&Arow[(r0+8)*NSEQ + colb + 8]   = w;
            unsigned pa[4];
            pa[0] = pack2(p[0][0], p[0][1]);
            pa[1] = pack2(p[0][2], p[0][3]);
            pa[2] = pack2(p[1][0], p[1][1]);
            pa[3] = pack2(p[1][2], p[1][3]);
#pragma unroll
            for (int njp = 0; njp < 4; njp++) {
                unsigned bv[4];
                ldm_x4t(bv, smem_u32(Vs + (kg*16 + lrow)*QP + (njp*2 + (lane>>4))*8));
                unsigned b0[2] = {bv[0], bv[1]}, b1[2] = {bv[2], bv[3]};
                mma_bf16(Macc[njp*2],     pa, b0);
                mma_bf16(Macc[njp*2 + 1], pa, b1);
            }
        }
        if (kt < 15) { cp_wait<0>(); __syncthreads(); }
    }

    lsum0 += __shfl_xor_sync(0xffffffff, lsum0, 1);
    lsum0 += __shfl_xor_sync(0xffffffff, lsum0, 2);
    lsum1 += __shfl_xor_sync(0xffffffff, lsum1, 1);
    lsum1 += __shfl_xor_sync(0xffffffff, lsum1, 2);
    float invl0 = 1.f / lsum0;
    float invl1 = 1.f / lsum1;

    if ((lane & 3) == 0) {
        long lrow0 = (long)bh * NSEQ + q0 + warp * 16 + (lane >> 2);
        Lg[lrow0]     = lsum0;
        Lg[lrow0 + 8] = lsum1;
    }

    long mrow0 = qrow + warp * 16 + (lane >> 2);
#pragma unroll
    for (int njv = 0; njv < 8; njv++) {
        int col = hh * HDM + njv * 8 + 2 * (lane & 3);
        bf162 ph;
        ph.x = __float2bfloat16_rn(Macc[njv][0] * invl0);
        ph.y = __float2bfloat16_rn(Macc[njv][1] * invl0);
        *(bf162*)&Mhg[mrow0 * DDIM + col] = ph;
        ph.x = __float2bfloat16_rn(Macc[njv][2] * invl1);
        ph.y = __float2bfloat16_rn(Macc[njv][3] * invl1);
        *(bf162*)&Mhg[(mrow0 + 8) * DDIM + col] = ph;
    }
}

// ---------------- elementwise kernels ----------------
__device__ __forceinline__ void split_body(const float* __restrict__ s,
                                           bf16* __restrict__ h, bf16* __restrict__ l,
                                           long i)
{
    float4 v = *(const float4*)(s + i);
    bf16 h0,l0,h1,l1,h2,l2,h3,l3;
    split_bf16(v.x, h0, l0); split_bf16(v.y, h1, l1);
    split_bf16(v.z, h2, l2); split_bf16(v.w, h3, l3);
    bf162 p;
    p.x = h0; p.y = h1; *(bf162*)(h + i)     = p;
    p.x = h2; p.y = h3; *(bf162*)(h + i + 2) = p;
    p.x = l0; p.y = l1; *(bf162*)(l + i)     = p;
    p.x = l2; p.y = l3; *(bf162*)(l + i + 2) = p;
}

__global__ void split_kernel(const float* __restrict__ s, bf16* __restrict__ h, bf16* __restrict__ l)
{
    long i = ((long)blockIdx.x * blockDim.x + threadIdx.x) * 4;
    split_body(s, h, l, i);
}

// multiplexed weight split: z picks source/destination
struct SplitP {
    const float* s[3];
    bf16* h[3]; bf16* l[3];
};
__global__ void split_multi_kernel(SplitP p)
{
    int z = blockIdx.z;
    long i = ((long)blockIdx.x * blockDim.x + threadIdx.x) * 4;
    split_body(p.s[z], p.h[z], p.l[z], i);
}

// VG = V * sigmoid(G) -> bf16 (hi only; PV path is damped)
__global__ void vg_kernel(const float* __restrict__ V, const float* __restrict__ G,
                          bf16* __restrict__ h)
{
    long i = ((long)blockIdx.x * blockDim.x + threadIdx.x) * 4;
    float4 v = *(const float4*)(V + i);
    float4 g = *(const float4*)(G + i);
    bf162 p;
    p.x = __float2bfloat16_rn(v.x * g.x);
    p.y = __float2bfloat16_rn(v.y * g.y);
    *(bf162*)(h + i) = p;
    p.x = __float2bfloat16_rn(v.z * g.z);
    p.y = __float2bfloat16_rn(v.w * g.w);
    *(bf162*)(h + i + 2) = p;
}

// LayerNorm over last dim (1024)
__global__ void ln_kernel(const float* __restrict__ Y,
                          const float* __restrict__ gamma,
                          const float* __restrict__ beta,
                          float* __restrict__ out)
{
    __shared__ float red[256];
    int row = blockIdx.x, tid = threadIdx.x;
    const float4* y4 = (const float4*)(Y + (long)row * DDIM);
    float4 v = y4[tid];

    red[tid] = v.x + v.y + v.z + v.w; __syncthreads();
    for (int o = 128; o > 0; o >>= 1) {
        if (tid < o) red[tid] += red[tid + o];
        __syncthreads();
    }
    float mean = red[0] * (1.f / DDIM);
    __syncthreads();

    float d0 = v.x - mean, d1 = v.y - mean, d2 = v.z - mean, d3 = v.w - mean;
    red[tid] = d0*d0 + d1*d1 + d2*d2 + d3*d3; __syncthreads();
    for (int o = 128; o > 0; o >>= 1) {
        if (tid < o) red[tid] += red[tid + o];
        __syncthreads();
    }
    float var = red[0] * (1.f / DDIM);
    float inv = rsqrtf(var + 1e-5f);

    float4 g  = ((const float4*)gamma)[tid];
    float4 bt = ((const float4*)beta)[tid];
    float4 o4;
    o4.x = g.x * (d0 * inv) + bt.x;
    o4.y = g.y * (d1 * inv) + bt.y;
    o4.z = g.z * (d2 * inv) + bt.z;
    o4.w = g.w * (d3 * inv) + bt.w;
    ((float4*)(out + (long)row * DDIM))[tid] = o4;
}

extern "C" void kernel_launch(void* const* d_in, const int* in_sizes, int n_in,
                              void* d_out, int out_size)
{
    const float* x     = (const float*)d_in[0];
    const float* Wq    = (const float*)d_in[1];
    const float* bq    = (const float*)d_in[2];
    const float* Wk    = (const float*)d_in[3];
    const float* bk    = (const float*)d_in[4];
    const float* Wv    = (const float*)d_in[5];
    const float* bv    = (const float*)d_in[6];
    const float* Wg    = (const float*)d_in[7];
    const float* bg    = (const float*)d_in[8];
    const float* Wp    = (const float*)d_in[9];
    const float* bp    = (const float*)d_in[10];
    const float* gamma = (const float*)d_in[11];
    const float* beta  = (const float*)d_in[12];
    float* outp = (float*)d_out;

    bf16 *xh, *xl, *wh, *wl, *Qh, *Ql, *Kh, *Kl, *VGh, *Mh;
    float *Vf, *Gf, *Y, *Lr, *Afb;
    cudaGetSymbolAddress((void**)&xh,  g_xh);
    cudaGetSymbolAddress((void**)&xl,  g_xl);
    cudaGetSymbolAddress((void**)&wh,  g_wh);
    cudaGetSymbolAddress((void**)&wl,  g_wl);
    cudaGetSymbolAddress((void**)&Qh,  g_Qh);
    cudaGetSymbolAddress((void**)&Ql,  g_Ql);
    cudaGetSymbolAddress((void**)&Kh,  g_Kh);
    cudaGetSymbolAddress((void**)&Kl,  g_Kl);
    cudaGetSymbolAddress((void**)&Vf,  g_V);
    cudaGetSymbolAddress((void**)&Gf,  g_G);
    cudaGetSymbolAddress((void**)&VGh, g_VGh);
    cudaGetSymbolAddress((void**)&Mh,  g_Mh);
    cudaGetSymbolAddress((void**)&Y,   g_Y);
    cudaGetSymbolAddress((void**)&Lr,  g_L);
    cudaGetSymbolAddress((void**)&Afb, g_Afb);

    float* A = ((long)out_size >= OUT1 + AELEMS) ? (outp + OUT1) : Afb;

    const long WSZ = (long)LDIM * DDIM;

    // launches 0-2: splits (x; Wq,Wk; Wv,Wg,Wp)
    split_kernel<<<(BNROWS*(long)LDIM)/1024, 256>>>(x, xh, xl);
    {
        SplitP p;
        p.s[0] = Wq; p.h[0] = wh + 0*WSZ; p.l[0] = wl + 0*WSZ;
        p.s[1] = Wk; p.h[1] = wh + 1*WSZ; p.l[1] = wl + 1*WSZ;
        p.s[2] = Wq; p.h[2] = wh + 0*WSZ; p.l[2] = wl + 0*WSZ; // unused
        dim3 g(WSZ/1024, 1, 2);
        split_multi_kernel<<<g, 256>>>(p);
    }
    {
        SplitP p;
        p.s[0] = Wv; p.h[0] = wh + 2*WSZ; p.l[0] = wl + 2*WSZ;
        p.s[1] = Wg; p.h[1] = wh + 3*WSZ; p.l[1] = wl + 3*WSZ;
        p.s[2] = Wp; p.h[2] = wh + 4*WSZ; p.l[2] = wl + 4*WSZ;
        dim3 g(WSZ/1024, 1, 3);
        split_multi_kernel<<<g, 256>>>(p);
    }

    constexpr int SM_PROJ = 2 * stage_bytes_h(128, 128, 32);
    constexpr int SM_ATTN = 110592;

    cudaFuncSetAttribute(gemm4_kernel<128,128,32,64,32>,
                         cudaFuncAttributeMaxDynamicSharedMemorySize, SM_PROJ);
    cudaFuncSetAttribute(gemm1norm_kernel<128,128,32,64,32>,
                         cudaFuncAttributeMaxDynamicSharedMemorySize, SM_PROJ);
    cudaFuncSetAttribute(attn_kernel,
                         cudaFuncAttributeMaxDynamicSharedMemorySize, SM_ATTN);

    // launch 3: fused projections
    {
        Ptrs4 p;
        p.Bh[0] = wh + 0*WSZ; p.Bl[0] = wl + 0*WSZ; p.bias[0] = bq;
        p.Cf[0] = nullptr; p.Ch[0] = Qh; p.Cl[0] = Ql; p.act[0] = 0; p.full[0] = 1;
        p.Bh[1] = wh + 1*WSZ; p.Bl[1] = wl + 1*WSZ; p.bias[1] = bk;
        p.Cf[1] = nullptr; p.Ch[1] = Kh; p.Cl[1] = Kl; p.act[1] = 0; p.full[1] = 1;
        p.Bh[2] = wh + 2*WSZ; p.Bl[2] = wl + 2*WSZ; p.bias[2] = bv;
        p.Cf[2] = Vf; p.Ch[2] = nullptr; p.Cl[2] = nullptr; p.act[2] = 0; p.full[2] = 0;
        p.Bh[3] = wh + 3*WSZ; p.Bl[3] = wl + 3*WSZ; p.bias[3] = bg;
        p.Cf[3] = Gf; p.Ch[3] = nullptr; p.Cl[3] = nullptr; p.act[3] = 1; p.full[3] = 0;
        dim3 grid(DDIM/128, BNROWS/128, 4);
        gemm4_kernel<128,128,32,64,32><<<grid, 256, SM_PROJ>>>(
            LDIM, xh, xl, LDIM, DDIM, DDIM, p);
    }

    // launch 4: VG
    vg_kernel<<<(BNROWS*(long)DDIM)/1024, 256>>>(Vf, Gf, VGh);

    // launch 5: fused single-pass attention (ncu -s 5 lands here)
    {
        dim3 grid(NSEQ/128, BDIM*HH);
        attn_kernel<<<grid, 256, SM_ATTN>>>(Qh, Ql, Kh, Kl, VGh, A, Lr, Mh);
    }

    // launch 6: out-projection GEMM (z=0) + A normalization (z=1), overlapped
    {
        dim3 grid(DDIM/128, BNROWS/128, 2);
        gemm1norm_kernel<128,128,32,64,32><<<grid, 256, SM_PROJ>>>(
            DDIM, 0,
            Mh, Mh, DDIM,
            wh + 4*WSZ, wl + 4*WSZ, DDIM,
            Y, DDIM, bp, x, DDIM,
            A, Lr);
    }

    // launch 7: LayerNorm -> out
    ln_kernel<<<BNROWS, 256>>>(Y, gamma, beta, outp);
}

// round 8
// speedup vs baseline: 1.2099x; 1.2099x over previous
#include <cuda_runtime.h>
#include <cuda_bf16.h>
#include <math.h>

#define BDIM 2
#define NSEQ 2048
#define LDIM 1024
#define DDIM 1024
#define HH   16
#define HDM  64
#define BNROWS (BDIM*NSEQ)   // 4096
#define SM_SCALE 0.125f

static const long OUT1   = (long)BDIM * NSEQ * DDIM;        // 4,194,304
static const long AELEMS = (long)BDIM * HH * NSEQ * NSEQ;   // 134,217,728

typedef __nv_bfloat16 bf16;
typedef __nv_bfloat162 bf162;

// ---------------- device scratch (no cudaMalloc anywhere) ----------------
__device__ __align__(256) bf16 g_xh[BNROWS*LDIM], g_xl[BNROWS*LDIM];
__device__ __align__(256) bf16 g_wh[5][LDIM*DDIM], g_wl[5][LDIM*DDIM];
__device__ __align__(256) bf16 g_Qh[BNROWS*DDIM], g_Ql[BNROWS*DDIM];
__device__ __align__(256) bf16 g_Kh[BNROWS*DDIM], g_Kl[BNROWS*DDIM];
__device__ float g_V[BNROWS*DDIM];
__device__ float g_G[BNROWS*DDIM];
__device__ __align__(256) bf16 g_VGh[BNROWS*DDIM];
__device__ __align__(256) bf16 g_Mh[BNROWS*DDIM];
__device__ float g_Y[BNROWS*DDIM];
__device__ float g_Afb[(size_t)BDIM*HH*NSEQ*NSEQ];  // fallback if A not in output

// ---------------- PTX helpers ----------------
__device__ __forceinline__ unsigned smem_u32(const void* p) {
    return (unsigned)__cvta_generic_to_shared(p);
}
__device__ __forceinline__ void cp16(unsigned dst, const void* src) {
    asm volatile("cp.async.ca.shared.global [%0], [%1], 16;\n" :: "r"(dst), "l"(src));
}
__device__ __forceinline__ void cp_commit() { asm volatile("cp.async.commit_group;\n" ::); }
template<int N> __device__ __forceinline__ void cp_wait() {
    asm volatile("cp.async.wait_group %0;\n" :: "n"(N));
}
__device__ __forceinline__ void ldm_x4(unsigned* d, unsigned addr) {
    asm volatile("ldmatrix.sync.aligned.m8n8.x4.shared.b16 {%0,%1,%2,%3}, [%4];"
                 : "=r"(d[0]), "=r"(d[1]), "=r"(d[2]), "=r"(d[3]) : "r"(addr));
}
__device__ __forceinline__ void ldm_x4t(unsigned* d, unsigned addr) {
    asm volatile("ldmatrix.sync.aligned.m8n8.x4.trans.shared.b16 {%0,%1,%2,%3}, [%4];"
                 : "=r"(d[0]), "=r"(d[1]), "=r"(d[2]), "=r"(d[3]) : "r"(addr));
}
__device__ __forceinline__ void mma_bf16(float* c, const unsigned* a, const unsigned* b) {
    asm volatile(
        "mma.sync.aligned.m16n8k16.row.col.f32.bf16.bf16.f32 "
        "{%0,%1,%2,%3},{%4,%5,%6,%7},{%8,%9},{%0,%1,%2,%3};"
        : "+f"(c[0]), "+f"(c[1]), "+f"(c[2]), "+f"(c[3])
        : "r"(a[0]), "r"(a[1]), "r"(a[2]), "r"(a[3]), "r"(b[0]), "r"(b[1]));
}
__device__ __forceinline__ void split_bf16(float v, bf16& h, bf16& l) {
    h = __float2bfloat16_rn(v);
    l = __float2bfloat16_rn(v - __bfloat162float(h));
}
__device__ __forceinline__ unsigned pack2(float a, float b) {
    bf162 t; t.x = __float2bfloat16_rn(a); t.y = __float2bfloat16_rn(b);
    return *(unsigned*)&t;
}

// ---------------------------------------------------------------------------
// GEMM body: bf16 tensor-core GEMM, cp.async 2-stage pipeline.
// full=true -> bf16x3 error-compensated (hi/lo). full=false -> hi-only.
// ---------------------------------------------------------------------------
template<int BM, int BN, int BK, int WM, int WN, int THREADS>
__device__ __forceinline__ void gemm_body(
    int K, bool full,
    const bf16* __restrict__ Agh, const bf16* __restrict__ Agl, int lda,
    const bf16* __restrict__ Bgh, const bf16* __restrict__ Bgl, int ldb,
    float* Cf, bf16* Ch, bf16* Cl, int ldc,
    const float* bias, const float* resid, int ldr,
    float alpha, int act)
{
    constexpr int APITCH = BK + 8;
    constexpr int BPITCH = BN + 8;
    constexpr int ABYTES = BM * APITCH * 2;
    constexpr int BBYTES = BK * BPITCH * 2;
    constexpr int STAGE  = 2 * ABYTES + 2 * BBYTES;
    constexpr int MI = WM / 16, NJ = WN / 8;

    extern __shared__ char dsm[];

    const int tid  = threadIdx.x;
    const int lane = tid & 31;
    const int warp = tid >> 5;
    const int wm = warp % (BM/WM);
    const int wn = warp / (BM/WM);
    const int m0 = wm * WM, n0 = wn * WN;
    const int rowBase = blockIdx.y * BM;
    const int colBase = blockIdx.x * BN;
    const int lrow  = lane & 15;
    const int lkoff = (lane >> 4) << 3;

    float acc[MI][NJ][4];
#pragma unroll
    for (int i = 0; i < MI; i++)
#pragma unroll
        for (int j = 0; j < NJ; j++)
#pragma unroll
            for (int q = 0; q < 4; q++) acc[i][j][q] = 0.f;

    auto load_stage = [&](int s, int k0) {
        char* base = dsm + s * STAGE;
        bf16* Ash = (bf16*)(base);
        bf16* Asl = (bf16*)(base + ABYTES);
        bf16* Bsh = (bf16*)(base + 2*ABYTES);
        bf16* Bsl = (bf16*)(base + 2*ABYTES + BBYTES);
        constexpr int ACH = BM * BK / 8;
#pragma unroll
        for (int t = 0; t < ACH; t += THREADS) {
            int idx = t + tid;
            int r = idx / (BK/8);
            int c = (idx % (BK/8)) * 8;
            long so = (long)(rowBase + r) * lda + k0 + c;
            cp16(smem_u32(Ash + r*APITCH + c), Agh + so);
            if (full) cp16(smem_u32(Asl + r*APITCH + c), Agl + so);
        }
        constexpr int BCH = BK * BN / 8;
#pragma unroll
        for (int t = 0; t < BCH; t += THREADS) {
            int idx = t + tid;
            int r = idx / (BN/8);
            int c = (idx % (BN/8)) * 8;
            long so = (long)(k0 + r) * ldb + colBase + c;
            cp16(smem_u32(Bsh + r*BPITCH + c), Bgh + so);
            if (full) cp16(smem_u32(Bsl + r*BPITCH + c), Bgl + so);
        }
    };

    auto compute_stage = [&](int s) {
        char* base = dsm + s * STAGE;
        bf16* Ash = (bf16*)(base);
        bf16* Asl = (bf16*)(base + ABYTES);
        bf16* Bsh = (bf16*)(base + 2*ABYTES);
        bf16* Bsl = (bf16*)(base + 2*ABYTES + BBYTES);
#pragma unroll
        for (int kk = 0; kk < BK; kk += 16) {
            unsigned afh[MI][4], afl[MI][4];
            unsigned bfh[NJ][2], bfl[NJ][2];
#pragma unroll
            for (int mi = 0; mi < MI; mi++) {
                ldm_x4(afh[mi], smem_u32(Ash + (m0 + mi*16 + lrow)*APITCH + kk + lkoff));
                if (full) ldm_x4(afl[mi], smem_u32(Asl + (m0 + mi*16 + lrow)*APITCH + kk + lkoff));
            }
#pragma unroll
            for (int nj = 0; nj < NJ; nj += 2) {
                ldm_x4t(&bfh[nj][0], smem_u32(Bsh + (kk + lrow)*BPITCH + n0 + (nj + (lane>>4))*8));
                if (full) ldm_x4t(&bfl[nj][0], smem_u32(Bsl + (kk + lrow)*BPITCH + n0 + (nj + (lane>>4))*8));
            }
#pragma unroll
            for (int mi = 0; mi < MI; mi++)
#pragma unroll
                for (int nj = 0; nj < NJ; nj++) {
                    mma_bf16(acc[mi][nj], afh[mi], bfh[nj]);
                    if (full) {
                        mma_bf16(acc[mi][nj], afh[mi], bfl[nj]);
                        mma_bf16(acc[mi][nj], afl[mi], bfh[nj]);
                    }
                }
        }
    };

    const int KT = K / BK;
    load_stage(0, 0);
    cp_commit();
    for (int kt = 0; kt < KT; kt++) {
        if (kt + 1 < KT) {
            load_stage((kt + 1) & 1, (kt + 1) * BK);
            cp_commit();
            cp_wait<1>();
        } else {
            cp_wait<0>();
        }
        __syncthreads();
        compute_stage(kt & 1);
        __syncthreads();
    }

    // ---- epilogue ----
#pragma unroll
    for (int mi = 0; mi < MI; mi++) {
#pragma unroll
        for (int nj = 0; nj < NJ; nj++) {
            int c = colBase + n0 + nj*8 + 2*(lane & 3);
            float b0 = 0.f, b1 = 0.f;
            if (bias) { b0 = bias[c]; b1 = bias[c+1]; }
#pragma unroll
            for (int half = 0; half < 2; half++) {
                int r = rowBase + m0 + mi*16 + (lane >> 2) + half*8;
                float v0 = acc[mi][nj][half*2+0] * alpha + b0;
                float v1 = acc[mi][nj][half*2+1] * alpha + b1;
                if (act == 1) {
                    v0 = 1.f / (1.f + __expf(-v0));
                    v1 = 1.f / (1.f + __expf(-v1));
                }
                if (resid) {
                    v0 += resid[(long)r * ldr + c];
                    v1 += resid[(long)r * ldr + c + 1];
                }
                long off = (long)r * ldc + c;
                if (Cf) {
                    float2 o; o.x = v0; o.y = v1;
                    *(float2*)&Cf[off] = o;
                }
                if (Ch) {
                    bf16 h0, l0, h1, l1;
                    split_bf16(v0, h0, l0);
                    split_bf16(v1, h1, l1);
                    bf162 ph; ph.x = h0; ph.y = h1;
                    bf162 pl; pl.x = l0; pl.y = l1;
                    *(bf162*)&Ch[off] = ph;
                    *(bf162*)&Cl[off] = pl;
                }
            }
        }
    }
}

// multiplexed 4-projection kernel
struct Ptrs4 {
    const bf16* Bh[4]; const bf16* Bl[4];
    const float* bias[4];
    float* Cf[4]; bf16* Ch[4]; bf16* Cl[4];
    int act[4]; int full[4];
};

template<int BM, int BN, int BK, int WM, int WN>
__global__ __launch_bounds__((BM/WM)*(BN/WN)*32, 2)
void gemm4_kernel(int K, const bf16* __restrict__ Ah, const bf16* __restrict__ Al,
                  int lda, int ldb, int ldc, Ptrs4 p)
{
    int z = blockIdx.z;
    gemm_body<BM,BN,BK,WM,WN,(BM/WM)*(BN/WN)*32>(
        K, p.full[z] != 0, Ah, Al, lda, p.Bh[z], p.Bl[z], ldb,
        p.Cf[z], p.Ch[z], p.Cl[z], ldc,
        p.bias[z], nullptr, 0, 1.f, p.act[z]);
}

// single GEMM (out projection)
template<int BM, int BN, int BK, int WM, int WN>
__global__ __launch_bounds__((BM/WM)*(BN/WN)*32, 2)
void gemm1_kernel(int K, int full,
                  const bf16* __restrict__ Ah, const bf16* __restrict__ Al, int lda,
                  const bf16* __restrict__ Bh, const bf16* __restrict__ Bl, int ldb,
                  float* Cf, int ldc,
                  const float* bias, const float* resid, int ldr)
{
    gemm_body<BM,BN,BK,WM,WN,(BM/WM)*(BN/WN)*32>(
        K, full != 0, Ah, Al, lda, Bh, Bl, ldb,
        Cf, nullptr, nullptr, ldc, bias, resid, ldr, 1.f, 0);
}

constexpr int stage_bytes_h(int BM, int BN, int BK) {
    return 2 * (BM * (BK + 8) * 2) + 2 * (BK * (BN + 8) * 2);
}

// ---------------------------------------------------------------------------
// Two-pass fused attention, per CTA = 128 query rows x one (b,h).
// Pass 1 (cheap): hi-only bf16 S, no max subtraction; per-thread partial sums
//   of exp(s*scale); errors average out in the 2048-term denominator (~1e-4).
// Pass 2 (accurate): bf16x3 S, P = exp(s*scale)/l, write normalized A once,
//   fused PV accumulate (hi-only, damped downstream).
// smem: Q hi/lo [0,36864); pass1 Kh double-buffer at 36864,55296 (18432 each);
//       pass2 stages (Kh/Kl 36864 + V 18432 = 55296) at 0 and 55296.
// ---------------------------------------------------------------------------
#define QP 72  // smem pitch (elems) for 64-wide tiles

__global__ __launch_bounds__(256, 2)
void attn_kernel(const bf16* __restrict__ Qhg, const bf16* __restrict__ Qlg,
                 const bf16* __restrict__ Khg, const bf16* __restrict__ Klg,
                 const bf16* __restrict__ Vhg,
                 float* __restrict__ Ag, bf16* __restrict__ Mhg)
{
    extern __shared__ char sm[];
    const int tid = threadIdx.x, lane = tid & 31, warp = tid >> 5;
    const int bh = blockIdx.y, bb = bh >> 4, hh = bh & 15;
    const int q0 = blockIdx.x * 128;
    const long qrow = (long)bb * NSEQ + q0;
    const bf16* Qh = Qhg + qrow * DDIM + hh * HDM;
    const bf16* Ql = Qlg + qrow * DDIM + hh * HDM;
    const bf16* Kh = Khg + (long)bb * NSEQ * DDIM + hh * HDM;
    const bf16* Kl = Klg + (long)bb * NSEQ * DDIM + hh * HDM;
    const bf16* Vh = Vhg + (long)bb * NSEQ * DDIM + hh * HDM;
    float* Arow = Ag + ((long)bh * NSEQ + q0) * NSEQ;

    bf16* Qs = (bf16*)sm;
    const int lrow = lane & 15, lk = (lane >> 4) * 8;

    auto loadQ = [&]() {
        for (int t = tid; t < 2048; t += 256) {
            int hl = t >> 10, rem = t & 1023, r = rem >> 3, c = (rem & 7) * 8;
            const bf16* s = (hl ? Ql : Qh) + (long)r * DDIM + c;
            cp16(smem_u32(Qs + hl * 128 * QP + r * QP + c), s);
        }
    };
    auto loadKh1 = [&](char* dst, int key0) {   // hi-only K tile (pass 1)
        for (int t = tid; t < 1024; t += 256) {
            int r = t >> 3, c = (t & 7) * 8;
            cp16(smem_u32((bf16*)dst + r * QP + c), Kh + (long)(key0 + r) * DDIM + c);
        }
    };
    auto loadKtile = [&](char* dst, int key0) { // hi+lo K tile (pass 2)
        for (int t = tid; t < 2048; t += 256) {
            int hl = t >> 10, rem = t & 1023, r = rem >> 3, c = (rem & 7) * 8;
            const bf16* s = (hl ? Kl : Kh) + (long)(key0 + r) * DDIM + c;
            cp16(smem_u32((bf16*)dst + hl * 128 * QP + r * QP + c), s);
        }
    };
    auto loadVtile = [&](char* dst, int key0) {
        for (int t = tid; t < 1024; t += 256) {
            int r = t >> 3, c = (t & 7) * 8;
            cp16(smem_u32((bf16*)dst + r * QP + c), Vh + (long)(key0 + r) * DDIM + c);
        }
    };

    // ---- prologue: Q + first pass-1 K tile ----
    loadQ();
    loadKh1(sm + 36864, 0);
    cp_commit(); cp_wait<0>(); __syncthreads();

    // preload Q fragments (constant through both passes)
    unsigned aqh[4][4], aql[4][4];
#pragma unroll
    for (int kk = 0; kk < 4; kk++) {
        ldm_x4(aqh[kk], smem_u32(Qs + (warp*16 + lrow)*QP + kk*16 + lk));
        ldm_x4(aql[kk], smem_u32(Qs + 128*QP + (warp*16 + lrow)*QP + kk*16 + lk));
    }

    // ---- pass 1: hi-only S, accumulate row sums of exp ----
    float lsum0 = 0.f, lsum1 = 0.f;
    for (int kt = 0; kt < 16; kt++) {
        char* cur = sm + 36864 + (kt & 1) * 18432;
        if (kt < 15) {
            loadKh1(sm + 36864 + ((kt + 1) & 1) * 18432, (kt + 1) * 128);
            cp_commit();
        }
#pragma unroll 1
        for (int kg = 0; kg < 8; kg++) {
            float c[2][4] = {};
            const bf16* Ksh = (const bf16*)cur;
#pragma unroll
            for (int kk = 0; kk < 4; kk++) {
                unsigned rh[4];
                ldm_x4(rh, smem_u32(Ksh + (kg*16 + lrow)*QP + kk*16 + lk));
                unsigned b0h[2] = {rh[0], rh[2]}, b1h[2] = {rh[1], rh[3]};
                mma_bf16(c[0], aqh[kk], b0h);
                mma_bf16(c[1], aqh[kk], b1h);
            }
            lsum0 += __expf(c[0][0]*SM_SCALE) + __expf(c[0][1]*SM_SCALE)
                   + __expf(c[1][0]*SM_SCALE) + __expf(c[1][1]*SM_SCALE);
            lsum1 += __expf(c[0][2]*SM_SCALE) + __expf(c[0][3]*SM_SCALE)
                   + __expf(c[1][2]*SM_SCALE) + __expf(c[1][3]*SM_SCALE);
        }
        if (kt < 15) { cp_wait<0>(); __syncthreads(); }
    }

    lsum0 += __shfl_xor_sync(0xffffffff, lsum0, 1);
    lsum0 += __shfl_xor_sync(0xffffffff, lsum0, 2);
    lsum1 += __shfl_xor_sync(0xffffffff, lsum1, 1);
    lsum1 += __shfl_xor_sync(0xffffffff, lsum1, 2);
    float invl0 = 1.f / lsum0;
    float invl1 = 1.f / lsum1;

    // ---- pass 2: bf16x3 S, write normalized A, fused PV ----
    __syncthreads();   // pass-1 buffers free before pass-2 overwrites
    loadKtile(sm + 55296, 0);
    loadVtile(sm + 55296 + 36864, 0);
    cp_commit(); cp_wait<0>(); __syncthreads();

    float Macc[8][4] = {};
    for (int kt = 0; kt < 16; kt++) {
        char* stg = sm + ((kt + 1) & 1) * 55296;
        if (kt < 15) {
            char* pre = sm + (kt & 1) * 55296;
            loadKtile(pre, (kt + 1) * 128);
            loadVtile(pre + 36864, (kt + 1) * 128);
            cp_commit();
        }
        const bf16* Vs = (const bf16*)(stg + 36864);
#pragma unroll 1
        for (int kg = 0; kg < 8; kg++) {
            float c[2][4] = {};
            const bf16* Ksh = (const bf16*)stg;
            const bf16* Ksl = Ksh + 128 * QP;
#pragma unroll
            for (int kk = 0; kk < 4; kk++) {
                unsigned rh[4], rl[4];
                ldm_x4(rh, smem_u32(Ksh + (kg*16 + lrow)*QP + kk*16 + lk));
                ldm_x4(rl, smem_u32(Ksl + (kg*16 + lrow)*QP + kk*16 + lk));
                unsigned b0h[2] = {rh[0], rh[2]}, b1h[2] = {rh[1], rh[3]};
                unsigned b0l[2] = {rl[0], rl[2]}, b1l[2] = {rl[1], rl[3]};
                mma_bf16(c[0], aqh[kk], b0h);
                mma_bf16(c[0], aqh[kk], b0l);
                mma_bf16(c[0], aql[kk], b0h);
                mma_bf16(c[1], aqh[kk], b1h);
                mma_bf16(c[1], aqh[kk], b1l);
                mma_bf16(c[1], aql[kk], b1h);
            }
            float p[2][4];
#pragma unroll
            for (int nj = 0; nj < 2; nj++) {
                p[nj][0] = __expf(c[nj][0] * SM_SCALE) * invl0;
                p[nj][1] = __expf(c[nj][1] * SM_SCALE) * invl0;
                p[nj][2] = __expf(c[nj][2] * SM_SCALE) * invl1;
                p[nj][3] = __expf(c[nj][3] * SM_SCALE) * invl1;
            }
            // write normalized A (fp32)
            long colb = (long)kt * 128 + kg * 16 + 2 * (lane & 3);
            long r0 = warp * 16 + (lane >> 2);
            float2 w;
            w.x = p[0][0]; w.y = p[0][1]; *(float2*)&Arow[r0*NSEQ + colb]           = w;
            w.x = p[1][0]; w.y = p[1][1]; *(float2*)&Arow[r0*NSEQ + colb + 8]       = w;
            w.x = p[0][2]; w.y = p[0][3]; *(float2*)&Arow[(r0+8)*NSEQ + colb]       = w;
            w.x = p[1][2]; w.y = p[1][3]; *(float2*)&Arow[(r0+8)*NSEQ + colb + 8]   = w;
            // repack normalized P as mma A-frag (hi-only; PV damped downstream)
            unsigned pa[4];
            pa[0] = pack2(p[0][0], p[0][1]);
            pa[1] = pack2(p[0][2], p[0][3]);
            pa[2] = pack2(p[1][0], p[1][1]);
            pa[3] = pack2(p[1][2], p[1][3]);
#pragma unroll
            for (int njp = 0; njp < 4; njp++) {
                unsigned bv[4];
                ldm_x4t(bv, smem_u32(Vs + (kg*16 + lrow)*QP + (njp*2 + (lane>>4))*8));
                unsigned b0[2] = {bv[0], bv[1]}, b1[2] = {bv[2], bv[3]};
                mma_bf16(Macc[njp*2],     pa, b0);
                mma_bf16(Macc[njp*2 + 1], pa, b1);
            }
        }
        if (kt < 15) { cp_wait<0>(); __syncthreads(); }
    }

    // ---- epilogue: M (already normalized) -> bf16 hi ----
    long mrow0 = qrow + warp * 16 + (lane >> 2);
#pragma unroll
    for (int njv = 0; njv < 8; njv++) {
        int col = hh * HDM + njv * 8 + 2 * (lane & 3);
        bf162 ph;
        ph.x = __float2bfloat16_rn(Macc[njv][0]);
        ph.y = __float2bfloat16_rn(Macc[njv][1]);
        *(bf162*)&Mhg[mrow0 * DDIM + col] = ph;
        ph.x = __float2bfloat16_rn(Macc[njv][2]);
        ph.y = __float2bfloat16_rn(Macc[njv][3]);
        *(bf162*)&Mhg[(mrow0 + 8) * DDIM + col] = ph;
    }
}

// ---------------- elementwise kernels ----------------
__device__ __forceinline__ void split_body(const float* __restrict__ s,
                                           bf16* __restrict__ h, bf16* __restrict__ l,
                                           long i)
{
    float4 v = *(const float4*)(s + i);
    bf16 h0,l0,h1,l1,h2,l2,h3,l3;
    split_bf16(v.x, h0, l0); split_bf16(v.y, h1, l1);
    split_bf16(v.z, h2, l2); split_bf16(v.w, h3, l3);
    bf162 p;
    p.x = h0; p.y = h1; *(bf162*)(h + i)     = p;
    p.x = h2; p.y = h3; *(bf162*)(h + i + 2) = p;
    p.x = l0; p.y = l1; *(bf162*)(l + i)     = p;
    p.x = l2; p.y = l3; *(bf162*)(l + i + 2) = p;
}

__global__ void split_kernel(const float* __restrict__ s, bf16* __restrict__ h, bf16* __restrict__ l)
{
    long i = ((long)blockIdx.x * blockDim.x + threadIdx.x) * 4;
    split_body(s, h, l, i);
}

struct SplitP {
    const float* s[3];
    bf16* h[3]; bf16* l[3];
};
__global__ void split_multi_kernel(SplitP p)
{
    int z = blockIdx.z;
    long i = ((long)blockIdx.x * blockDim.x + threadIdx.x) * 4;
    split_body(p.s[z], p.h[z], p.l[z], i);
}

// VG = V * sigmoid(G) -> bf16 (hi only; PV path is damped)
__global__ void vg_kernel(const float* __restrict__ V, const float* __restrict__ G,
                          bf16* __restrict__ h)
{
    long i = ((long)blockIdx.x * blockDim.x + threadIdx.x) * 4;
    float4 v = *(const float4*)(V + i);
    float4 g = *(const float4*)(G + i);
    bf162 p;
    p.x = __float2bfloat16_rn(v.x * g.x);
    p.y = __float2bfloat16_rn(v.y * g.y);
    *(bf162*)(h + i) = p;
    p.x = __float2bfloat16_rn(v.z * g.z);
    p.y = __float2bfloat16_rn(v.w * g.w);
    *(bf162*)(h + i + 2) = p;
}

// LayerNorm over last dim (1024)
__global__ void ln_kernel(const float* __restrict__ Y,
                          const float* __restrict__ gamma,
                          const float* __restrict__ beta,
                          float* __restrict__ out)
{
    __shared__ float red[256];
    int row = blockIdx.x, tid = threadIdx.x;
    const float4* y4 = (const float4*)(Y + (long)row * DDIM);
    float4 v = y4[tid];

    red[tid] = v.x + v.y + v.z + v.w; __syncthreads();
    for (int o = 128; o > 0; o >>= 1) {
        if (tid < o) red[tid] += red[tid + o];
        __syncthreads();
    }
    float mean = red[0] * (1.f / DDIM);
    __syncthreads();

    float d0 = v.x - mean, d1 = v.y - mean, d2 = v.z - mean, d3 = v.w - mean;
    red[tid] = d0*d0 + d1*d1 + d2*d2 + d3*d3; __syncthreads();
    for (int o = 128; o > 0; o >>= 1) {
        if (tid < o) red[tid] += red[tid + o];
        __syncthreads();
    }
    float var = red[0] * (1.f / DDIM);
    float inv = rsqrtf(var + 1e-5f);

    float4 g  = ((const float4*)gamma)[tid];
    float4 bt = ((const float4*)beta)[tid];
    float4 o4;
    o4.x = g.x * (d0 * inv) + bt.x;
    o4.y = g.y * (d1 * inv) + bt.y;
    o4.z = g.z * (d2 * inv) + bt.z;
    o4.w = g.w * (d3 * inv) + bt.w;
    ((float4*)(out + (long)row * DDIM))[tid] = o4;
}

extern "C" void kernel_launch(void* const* d_in, const int* in_sizes, int n_in,
                              void* d_out, int out_size)
{
    const float* x     = (const float*)d_in[0];
    const float* Wq    = (const float*)d_in[1];
    const float* bq    = (const float*)d_in[2];
    const float* Wk    = (const float*)d_in[3];
    const float* bk    = (const float*)d_in[4];
    const float* Wv    = (const float*)d_in[5];
    const float* bv    = (const float*)d_in[6];
    const float* Wg    = (const float*)d_in[7];
    const float* bg    = (const float*)d_in[8];
    const float* Wp    = (const float*)d_in[9];
    const float* bp    = (const float*)d_in[10];
    const float* gamma = (const float*)d_in[11];
    const float* beta  = (const float*)d_in[12];
    float* outp = (float*)d_out;

    bf16 *xh, *xl, *wh, *wl, *Qh, *Ql, *Kh, *Kl, *VGh, *Mh;
    float *Vf, *Gf, *Y, *Afb;
    cudaGetSymbolAddress((void**)&xh,  g_xh);
    cudaGetSymbolAddress((void**)&xl,  g_xl);
    cudaGetSymbolAddress((void**)&wh,  g_wh);
    cudaGetSymbolAddress((void**)&wl,  g_wl);
    cudaGetSymbolAddress((void**)&Qh,  g_Qh);
    cudaGetSymbolAddress((void**)&Ql,  g_Ql);
    cudaGetSymbolAddress((void**)&Kh,  g_Kh);
    cudaGetSymbolAddress((void**)&Kl,  g_Kl);
    cudaGetSymbolAddress((void**)&Vf,  g_V);
    cudaGetSymbolAddress((void**)&Gf,  g_G);
    cudaGetSymbolAddress((void**)&VGh, g_VGh);
    cudaGetSymbolAddress((void**)&Mh,  g_Mh);
    cudaGetSymbolAddress((void**)&Y,   g_Y);
    cudaGetSymbolAddress((void**)&Afb, g_Afb);

    float* A = ((long)out_size >= OUT1 + AELEMS) ? (outp + OUT1) : Afb;

    const long WSZ = (long)LDIM * DDIM;

    // launches 0-2: splits (x; Wq,Wk; Wv,Wg,Wp)
    split_kernel<<<(BNROWS*(long)LDIM)/1024, 256>>>(x, xh, xl);
    {
        SplitP p;
        p.s[0] = Wq; p.h[0] = wh + 0*WSZ; p.l[0] = wl + 0*WSZ;
        p.s[1] = Wk; p.h[1] = wh + 1*WSZ; p.l[1] = wl + 1*WSZ;
        p.s[2] = Wq; p.h[2] = wh + 0*WSZ; p.l[2] = wl + 0*WSZ; // unused
        dim3 g(WSZ/1024, 1, 2);
        split_multi_kernel<<<g, 256>>>(p);
    }
    {
        SplitP p;
        p.s[0] = Wv; p.h[0] = wh + 2*WSZ; p.l[0] = wl + 2*WSZ;
        p.s[1] = Wg; p.h[1] = wh + 3*WSZ; p.l[1] = wl + 3*WSZ;
        p.s[2] = Wp; p.h[2] = wh + 4*WSZ; p.l[2] = wl + 4*WSZ;
        dim3 g(WSZ/1024, 1, 3);
        split_multi_kernel<<<g, 256>>>(p);
    }

    constexpr int SM_PROJ = 2 * stage_bytes_h(128, 128, 32);
    constexpr int SM_ATTN = 110592;

    cudaFuncSetAttribute(gemm4_kernel<128,128,32,64,32>,
                         cudaFuncAttributeMaxDynamicSharedMemorySize, SM_PROJ);
    cudaFuncSetAttribute(gemm1_kernel<128,128,32,64,32>,
                         cudaFuncAttributeMaxDynamicSharedMemorySize, SM_PROJ);
    cudaFuncSetAttribute(attn_kernel,
                         cudaFuncAttributeMaxDynamicSharedMemorySize, SM_ATTN);

    // launch 3: fused projections
    {
        Ptrs4 p;
        p.Bh[0] = wh + 0*WSZ; p.Bl[0] = wl + 0*WSZ; p.bias[0] = bq;
        p.Cf[0] = nullptr; p.Ch[0] = Qh; p.Cl[0] = Ql; p.act[0] = 0; p.full[0] = 1;
        p.Bh[1] = wh + 1*WSZ; p.Bl[1] = wl + 1*WSZ; p.bias[1] = bk;
        p.Cf[1] = nullptr; p.Ch[1] = Kh; p.Cl[1] = Kl; p.act[1] = 0; p.full[1] = 1;
        p.Bh[2] = wh + 2*WSZ; p.Bl[2] = wl + 2*WSZ; p.bias[2] = bv;
        p.Cf[2] = Vf; p.Ch[2] = nullptr; p.Cl[2] = nullptr; p.act[2] = 0; p.full[2] = 0;
        p.Bh[3] = wh + 3*WSZ; p.Bl[3] = wl + 3*WSZ; p.bias[3] = bg;
        p.Cf[3] = Gf; p.Ch[3] = nullptr; p.Cl[3] = nullptr; p.act[3] = 1; p.full[3] = 0;
        dim3 grid(DDIM/128, BNROWS/128, 4);
        gemm4_kernel<128,128,32,64,32><<<grid, 256, SM_PROJ>>>(
            LDIM, xh, xl, LDIM, DDIM, DDIM, p);
    }

    // launch 4: VG
    vg_kernel<<<(BNROWS*(long)DDIM)/1024, 256>>>(Vf, Gf, VGh);

    // launch 5: two-pass fused attention (ncu -s 5 lands here)
    {
        dim3 grid(NSEQ/128, BDIM*HH);
        attn_kernel<<<grid, 256, SM_ATTN>>>(Qh, Ql, Kh, Kl, VGh, A, Mh);
    }

    // launch 6: Y = x + M @ Wp + bp (hi-only; damped by residual)
    {
        dim3 grid(DDIM/128, BNROWS/128, 1);
        gemm1_kernel<128,128,32,64,32><<<grid, 256, SM_PROJ>>>(
            DDIM, 0,
            Mh, Mh, DDIM,
            wh + 4*WSZ, wl + 4*WSZ, DDIM,
            Y, DDIM, bp, x, DDIM);
    }

    // launch 7: LayerNorm -> out
    ln_kernel<<<BNROWS, 256>>>(Y, gamma, beta, outp);
}

// round 10
// speedup vs baseline: 1.2402x; 1.0250x over previous
#include <cuda_runtime.h>
#include <cuda_bf16.h>
#include <math.h>

#define BDIM 2
#define NSEQ 2048
#define LDIM 1024
#define DDIM 1024
#define HH   16
#define HDM  64
#define BNROWS (BDIM*NSEQ)   // 4096
#define SM_SCALE 0.125f

static const long OUT1   = (long)BDIM * NSEQ * DDIM;        // 4,194,304
static const long AELEMS = (long)BDIM * HH * NSEQ * NSEQ;   // 134,217,728

typedef __nv_bfloat16 bf16;
typedef __nv_bfloat162 bf162;

// ---------------- device scratch (no cudaMalloc anywhere) ----------------
__device__ __align__(256) bf16 g_xh[BNROWS*LDIM], g_xl[BNROWS*LDIM];
__device__ __align__(256) bf16 g_wh[5][LDIM*DDIM], g_wl[5][LDIM*DDIM];
__device__ __align__(256) bf16 g_Qh[BNROWS*DDIM], g_Ql[BNROWS*DDIM];
__device__ __align__(256) bf16 g_Kh[BNROWS*DDIM], g_Kl[BNROWS*DDIM];
__device__ float g_V[BNROWS*DDIM];
__device__ float g_G[BNROWS*DDIM];
__device__ __align__(256) bf16 g_VGh[BNROWS*DDIM];
__device__ __align__(256) bf16 g_Mh[BNROWS*DDIM];
__device__ float g_Y[BNROWS*DDIM];
__device__ float g_Afb[(size_t)BDIM*HH*NSEQ*NSEQ];  // fallback if A not in output

// ---------------- PTX helpers ----------------
__device__ __forceinline__ unsigned smem_u32(const void* p) {
    return (unsigned)__cvta_generic_to_shared(p);
}
__device__ __forceinline__ void cp16(unsigned dst, const void* src) {
    asm volatile("cp.async.ca.shared.global [%0], [%1], 16;\n" :: "r"(dst), "l"(src));
}
__device__ __forceinline__ void cp_commit() { asm volatile("cp.async.commit_group;\n" ::); }
template<int N> __device__ __forceinline__ void cp_wait() {
    asm volatile("cp.async.wait_group %0;\n" :: "n"(N));
}
__device__ __forceinline__ void ldm_x4(unsigned* d, unsigned addr) {
    asm volatile("ldmatrix.sync.aligned.m8n8.x4.shared.b16 {%0,%1,%2,%3}, [%4];"
                 : "=r"(d[0]), "=r"(d[1]), "=r"(d[2]), "=r"(d[3]) : "r"(addr));
}
__device__ __forceinline__ void ldm_x4t(unsigned* d, unsigned addr) {
    asm volatile("ldmatrix.sync.aligned.m8n8.x4.trans.shared.b16 {%0,%1,%2,%3}, [%4];"
                 : "=r"(d[0]), "=r"(d[1]), "=r"(d[2]), "=r"(d[3]) : "r"(addr));
}
__device__ __forceinline__ void mma_bf16(float* c, const unsigned* a, const unsigned* b) {
    asm volatile(
        "mma.sync.aligned.m16n8k16.row.col.f32.bf16.bf16.f32 "
        "{%0,%1,%2,%3},{%4,%5,%6,%7},{%8,%9},{%0,%1,%2,%3};"
        : "+f"(c[0]), "+f"(c[1]), "+f"(c[2]), "+f"(c[3])
        : "r"(a[0]), "r"(a[1]), "r"(a[2]), "r"(a[3]), "r"(b[0]), "r"(b[1]));
}
__device__ __forceinline__ void split_bf16(float v, bf16& h, bf16& l) {
    h = __float2bfloat16_rn(v);
    l = __float2bfloat16_rn(v - __bfloat162float(h));
}
__device__ __forceinline__ unsigned pack2(float a, float b) {
    bf162 t; t.x = __float2bfloat16_rn(a); t.y = __float2bfloat16_rn(b);
    return *(unsigned*)&t;
}

// SW128 XOR swizzle (byte offsets within a 1024B-aligned 128B-row tile)
#define SWZ(o) ((unsigned)(o) ^ ((((unsigned)(o)) >> 3) & 0x70))

// ---------------------------------------------------------------------------
// GEMM body: bf16 tensor-core GEMM, cp.async 2-stage pipeline, ONE sync/chunk.
// full=true -> bf16x3 error-compensated (hi/lo). full=false -> hi-only.
// ---------------------------------------------------------------------------
template<int BM, int BN, int BK, int WM, int WN, int THREADS>
__device__ __forceinline__ void gemm_body(
    int K, bool full,
    const bf16* __restrict__ Agh, const bf16* __restrict__ Agl, int lda,
    const bf16* __restrict__ Bgh, const bf16* __restrict__ Bgl, int ldb,
    float* Cf, bf16* Ch, bf16* Cl, int ldc,
    const float* bias, const float* resid, int ldr,
    float alpha, int act)
{
    constexpr int APITCH = BK + 8;
    constexpr int BPITCH = BN + 8;
    constexpr int ABYTES = BM * APITCH * 2;
    constexpr int BBYTES = BK * BPITCH * 2;
    constexpr int STAGE  = 2 * ABYTES + 2 * BBYTES;
    constexpr int MI = WM / 16, NJ = WN / 8;

    extern __shared__ char dsm[];

    const int tid  = threadIdx.x;
    const int lane = tid & 31;
    const int warp = tid >> 5;
    const int wm = warp % (BM/WM);
    const int wn = warp / (BM/WM);
    const int m0 = wm * WM, n0 = wn * WN;
    const int rowBase = blockIdx.y * BM;
    const int colBase = blockIdx.x * BN;
    const int lrow  = lane & 15;
    const int lkoff = (lane >> 4) << 3;

    float acc[MI][NJ][4];
#pragma unroll
    for (int i = 0; i < MI; i++)
#pragma unroll
        for (int j = 0; j < NJ; j++)
#pragma unroll
            for (int q = 0; q < 4; q++) acc[i][j][q] = 0.f;

    auto load_stage = [&](int s, int k0) {
        char* base = dsm + s * STAGE;
        bf16* Ash = (bf16*)(base);
        bf16* Asl = (bf16*)(base + ABYTES);
        bf16* Bsh = (bf16*)(base + 2*ABYTES);
        bf16* Bsl = (bf16*)(base + 2*ABYTES + BBYTES);
        constexpr int ACH = BM * BK / 8;
#pragma unroll
        for (int t = 0; t < ACH; t += THREADS) {
            int idx = t + tid;
            int r = idx / (BK/8);
            int c = (idx % (BK/8)) * 8;
            long so = (long)(rowBase + r) * lda + k0 + c;
            cp16(smem_u32(Ash + r*APITCH + c), Agh + so);
            if (full) cp16(smem_u32(Asl + r*APITCH + c), Agl + so);
        }
        constexpr int BCH = BK * BN / 8;
#pragma unroll
        for (int t = 0; t < BCH; t += THREADS) {
            int idx = t + tid;
            int r = idx / (BN/8);
            int c = (idx % (BN/8)) * 8;
            long so = (long)(k0 + r) * ldb + colBase + c;
            cp16(smem_u32(Bsh + r*BPITCH + c), Bgh + so);
            if (full) cp16(smem_u32(Bsl + r*BPITCH + c), Bgl + so);
        }
    };

    auto compute_stage = [&](int s) {
        char* base = dsm + s * STAGE;
        bf16* Ash = (bf16*)(base);
        bf16* Asl = (bf16*)(base + ABYTES);
        bf16* Bsh = (bf16*)(base + 2*ABYTES);
        bf16* Bsl = (bf16*)(base + 2*ABYTES + BBYTES);
#pragma unroll
        for (int kk = 0; kk < BK; kk += 16) {
            unsigned afh[MI][4], afl[MI][4];
            unsigned bfh[NJ][2], bfl[NJ][2];
#pragma unroll
            for (int mi = 0; mi < MI; mi++) {
                ldm_x4(afh[mi], smem_u32(Ash + (m0 + mi*16 + lrow)*APITCH + kk + lkoff));
                if (full) ldm_x4(afl[mi], smem_u32(Asl + (m0 + mi*16 + lrow)*APITCH + kk + lkoff));
            }
#pragma unroll
            for (int nj = 0; nj < NJ; nj += 2) {
                ldm_x4t(&bfh[nj][0], smem_u32(Bsh + (kk + lrow)*BPITCH + n0 + (nj + (lane>>4))*8));
                if (full) ldm_x4t(&bfl[nj][0], smem_u32(Bsl + (kk + lrow)*BPITCH + n0 + (nj + (lane>>4))*8));
            }
#pragma unroll
            for (int mi = 0; mi < MI; mi++)
#pragma unroll
                for (int nj = 0; nj < NJ; nj++) {
                    mma_bf16(acc[mi][nj], afh[mi], bfh[nj]);
                    if (full) {
                        mma_bf16(acc[mi][nj], afh[mi], bfl[nj]);
                        mma_bf16(acc[mi][nj], afl[mi], bfh[nj]);
                    }
                }
        }
    };

    const int KT = K / BK;
    load_stage(0, 0);
    cp_commit();
    // ONE barrier per chunk: wait(own copies) -> sync -> issue next load -> compute.
    // Safe: all warps passed sync => all finished compute(kt-1), whose slot the
    // new load overwrites.
    for (int kt = 0; kt < KT; kt++) {
        cp_wait<0>();
        __syncthreads();
        if (kt + 1 < KT) {
            load_stage((kt + 1) & 1, (kt + 1) * BK);
            cp_commit();
        }
        compute_stage(kt & 1);
    }

    // ---- epilogue ----
#pragma unroll
    for (int mi = 0; mi < MI; mi++) {
#pragma unroll
        for (int nj = 0; nj < NJ; nj++) {
            int c = colBase + n0 + nj*8 + 2*(lane & 3);
            float b0 = 0.f, b1 = 0.f;
            if (bias) { b0 = bias[c]; b1 = bias[c+1]; }
#pragma unroll
            for (int half = 0; half < 2; half++) {
                int r = rowBase + m0 + mi*16 + (lane >> 2) + half*8;
                float v0 = acc[mi][nj][half*2+0] * alpha + b0;
                float v1 = acc[mi][nj][half*2+1] * alpha + b1;
                if (act == 1) {
                    v0 = 1.f / (1.f + __expf(-v0));
                    v1 = 1.f / (1.f + __expf(-v1));
                }
                if (resid) {
                    v0 += resid[(long)r * ldr + c];
                    v1 += resid[(long)r * ldr + c + 1];
                }
                long off = (long)r * ldc + c;
                if (Cf) {
                    float2 o; o.x = v0; o.y = v1;
                    *(float2*)&Cf[off] = o;
                }
                if (Ch) {
                    bf16 h0, l0, h1, l1;
                    split_bf16(v0, h0, l0);
                    split_bf16(v1, h1, l1);
                    bf162 ph; ph.x = h0; ph.y = h1;
                    bf162 pl; pl.x = l0; pl.y = l1;
                    *(bf162*)&Ch[off] = ph;
                    *(bf162*)&Cl[off] = pl;
                }
            }
        }
    }
}

// multiplexed 4-projection kernel
struct Ptrs4 {
    const bf16* Bh[4]; const bf16* Bl[4];
    const float* bias[4];
    float* Cf[4]; bf16* Ch[4]; bf16* Cl[4];
    int act[4]; int full[4];
};

template<int BM, int BN, int BK, int WM, int WN>
__global__ __launch_bounds__((BM/WM)*(BN/WN)*32, 2)
void gemm4_kernel(int K, const bf16* __restrict__ Ah, const bf16* __restrict__ Al,
                  int lda, int ldb, int ldc, Ptrs4 p)
{
    int z = blockIdx.z;
    gemm_body<BM,BN,BK,WM,WN,(BM/WM)*(BN/WN)*32>(
        K, p.full[z] != 0, Ah, Al, lda, p.Bh[z], p.Bl[z], ldb,
        p.Cf[z], p.Ch[z], p.Cl[z], ldc,
        p.bias[z], nullptr, 0, 1.f, p.act[z]);
}

// single GEMM (out projection)
template<int BM, int BN, int BK, int WM, int WN>
__global__ __launch_bounds__((BM/WM)*(BN/WN)*32, 2)
void gemm1_kernel(int K, int full,
                  const bf16* __restrict__ Ah, const bf16* __restrict__ Al, int lda,
                  const bf16* __restrict__ Bh, const bf16* __restrict__ Bl, int ldb,
                  float* Cf, int ldc,
                  const float* bias, const float* resid, int ldr)
{
    gemm_body<BM,BN,BK,WM,WN,(BM/WM)*(BN/WN)*32>(
        K, full != 0, Ah, Al, lda, Bh, Bl, ldb,
        Cf, nullptr, nullptr, ldc, bias, resid, ldr, 1.f, 0);
}

constexpr int stage_bytes_h(int BM, int BN, int BK) {
    return 2 * (BM * (BK + 8) * 2) + 2 * (BK * (BN + 8) * 2);
}

// ---------------------------------------------------------------------------
// Two-pass fused attention with SW128-swizzled smem (128B rows, no padding):
// smem total 98304B -> 2 CTAs/SM (was 110592 -> 1 CTA/SM).
// Layout (1024B-aligned tiles of 16384B = 128 rows x 128B):
//   Q hi [0,16384), Q lo [16384,32768)          (used until frag preload)
//   pass1 Kh double buffer: 32768 + s*16384
//   pass2 stage s at s*49152: Kh +0, Kl +16384, V +32768
// Pass 1: hi-only S -> row sums of exp (errors average out, ~1e-4).
// Pass 2: bf16x3 S -> normalized A write + fused PV.
// ---------------------------------------------------------------------------
__global__ __launch_bounds__(256, 2)
void attn_kernel(const bf16* __restrict__ Qhg, const bf16* __restrict__ Qlg,
                 const bf16* __restrict__ Khg, const bf16* __restrict__ Klg,
                 const bf16* __restrict__ Vhg,
                 float* __restrict__ Ag, bf16* __restrict__ Mhg)
{
    extern __shared__ char sm[];
    const unsigned sb = smem_u32(sm);
    const int tid = threadIdx.x, lane = tid & 31, warp = tid >> 5;
    const int bh = blockIdx.y, bb = bh >> 4, hh = bh & 15;
    const int q0 = blockIdx.x * 128;
    const long qrow = (long)bb * NSEQ + q0;
    const bf16* Qh = Qhg + qrow * DDIM + hh * HDM;
    const bf16* Ql = Qlg + qrow * DDIM + hh * HDM;
    const bf16* Kh = Khg + (long)bb * NSEQ * DDIM + hh * HDM;
    const bf16* Kl = Klg + (long)bb * NSEQ * DDIM + hh * HDM;
    const bf16* Vh = Vhg + (long)bb * NSEQ * DDIM + hh * HDM;
    float* Arow = Ag + ((long)bh * NSEQ + q0) * NSEQ;

    const int lrow = lane & 15, lk = (lane >> 4) * 8;

    auto loadQ = [&]() {
        for (int t = tid; t < 2048; t += 256) {
            int hl = t >> 10, rem = t & 1023, r = rem >> 3, c = (rem & 7) * 8;
            const bf16* s = (hl ? Ql : Qh) + (long)r * DDIM + c;
            cp16(sb + hl * 16384 + SWZ(r * 128 + c * 2), s);
        }
    };
    auto loadK1 = [&](unsigned dst, int key0) {     // hi-only K tile (pass 1)
        for (int t = tid; t < 1024; t += 256) {
            int r = t >> 3, c = (t & 7) * 8;
            cp16(dst + SWZ(r * 128 + c * 2), Kh + (long)(key0 + r) * DDIM + c);
        }
    };
    auto loadK2 = [&](unsigned dst, int key0) {     // hi+lo K tile (pass 2)
        for (int t = tid; t < 2048; t += 256) {
            int hl = t >> 10, rem = t & 1023, r = rem >> 3, c = (rem & 7) * 8;
            const bf16* s = (hl ? Kl : Kh) + (long)(key0 + r) * DDIM + c;
            cp16(dst + hl * 16384 + SWZ(r * 128 + c * 2), s);
        }
    };
    auto loadV = [&](unsigned dst, int key0) {
        for (int t = tid; t < 1024; t += 256) {
            int r = t >> 3, c = (t & 7) * 8;
            cp16(dst + SWZ(r * 128 + c * 2), Vh + (long)(key0 + r) * DDIM + c);
        }
    };

    // ---- prologue: Q + first pass-1 K tile ----
    loadQ();
    loadK1(sb + 32768, 0);
    cp_commit(); cp_wait<0>(); __syncthreads();

    // preload Q fragments (constant through both passes)
    unsigned aqh[4][4], aql[4][4];
#pragma unroll
    for (int kk = 0; kk < 4; kk++) {
        unsigned off = SWZ((warp*16 + lrow) * 128 + (kk*16 + lk) * 2);
        ldm_x4(aqh[kk], sb + off);
        ldm_x4(aql[kk], sb + 16384 + off);
    }

    // ---- pass 1: hi-only S, row sums of exp ----
    float lsum0 = 0.f, lsum1 = 0.f;
    for (int kt = 0; kt < 16; kt++) {
        unsigned cur = sb + 32768 + (kt & 1) * 16384;
        if (kt < 15) {
            loadK1(sb + 32768 + ((kt + 1) & 1) * 16384, (kt + 1) * 128);
            cp_commit();
        }
#pragma unroll 1
        for (int kg = 0; kg < 8; kg++) {
            float c[2][4] = {};
#pragma unroll
            for (int kk = 0; kk < 4; kk++) {
                unsigned rh[4];
                ldm_x4(rh, cur + SWZ((kg*16 + lrow) * 128 + (kk*16 + lk) * 2));
                unsigned b0h[2] = {rh[0], rh[2]}, b1h[2] = {rh[1], rh[3]};
                mma_bf16(c[0], aqh[kk], b0h);
                mma_bf16(c[1], aqh[kk], b1h);
            }
            lsum0 += __expf(c[0][0]*SM_SCALE) + __expf(c[0][1]*SM_SCALE)
                   + __expf(c[1][0]*SM_SCALE) + __expf(c[1][1]*SM_SCALE);
            lsum1 += __expf(c[0][2]*SM_SCALE) + __expf(c[0][3]*SM_SCALE)
                   + __expf(c[1][2]*SM_SCALE) + __expf(c[1][3]*SM_SCALE);
        }
        if (kt < 15) { cp_wait<0>(); __syncthreads(); }
    }

    lsum0 += __shfl_xor_sync(0xffffffff, lsum0, 1);
    lsum0 += __shfl_xor_sync(0xffffffff, lsum0, 2);
    lsum1 += __shfl_xor_sync(0xffffffff, lsum1, 1);
    lsum1 += __shfl_xor_sync(0xffffffff, lsum1, 2);
    float invl0 = 1.f / lsum0;
    float invl1 = 1.f / lsum1;

    // ---- pass 2: bf16x3 S, write normalized A, fused PV ----
    __syncthreads();   // pass-1 buffers and Q region free
    loadK2(sb + 0, 0);
    loadV(sb + 32768, 0);
    cp_commit(); cp_wait<0>(); __syncthreads();

    float Macc[8][4] = {};
    for (int kt = 0; kt < 16; kt++) {
        unsigned stg = sb + (kt & 1) * 49152;
        if (kt < 15) {
            unsigned pre = sb + ((kt + 1) & 1) * 49152;
            loadK2(pre, (kt + 1) * 128);
            loadV(pre + 32768, (kt + 1) * 128);
            cp_commit();
        }
        unsigned Vs = stg + 32768;
#pragma unroll 1
        for (int kg = 0; kg < 8; kg++) {
            float c[2][4] = {};
#pragma unroll
            for (int kk = 0; kk < 4; kk++) {
                unsigned rh[4], rl[4];
                unsigned off = SWZ((kg*16 + lrow) * 128 + (kk*16 + lk) * 2);
                ldm_x4(rh, stg + off);
                ldm_x4(rl, stg + 16384 + off);
                unsigned b0h[2] = {rh[0], rh[2]}, b1h[2] = {rh[1], rh[3]};
                unsigned b0l[2] = {rl[0], rl[2]}, b1l[2] = {rl[1], rl[3]};
                mma_bf16(c[0], aqh[kk], b0h);
                mma_bf16(c[0], aqh[kk], b0l);
                mma_bf16(c[0], aql[kk], b0h);
                mma_bf16(c[1], aqh[kk], b1h);
                mma_bf16(c[1], aqh[kk], b1l);
                mma_bf16(c[1], aql[kk], b1h);
            }
            float p[2][4];
#pragma unroll
            for (int nj = 0; nj < 2; nj++) {
                p[nj][0] = __expf(c[nj][0] * SM_SCALE) * invl0;
                p[nj][1] = __expf(c[nj][1] * SM_SCALE) * invl0;
                p[nj][2] = __expf(c[nj][2] * SM_SCALE) * invl1;
                p[nj][3] = __expf(c[nj][3] * SM_SCALE) * invl1;
            }
            long colb = (long)kt * 128 + kg * 16 + 2 * (lane & 3);
            long r0 = warp * 16 + (lane >> 2);
            float2 w;
            w.x = p[0][0]; w.y = p[0][1]; *(float2*)&Arow[r0*NSEQ + colb]           = w;
            w.x = p[1][0]; w.y = p[1][1]; *(float2*)&Arow[r0*NSEQ + colb + 8]       = w;
            w.x = p[0][2]; w.y = p[0][3]; *(float2*)&Arow[(r0+8)*NSEQ + colb]       = w;
            w.x = p[1][2]; w.y = p[1][3]; *(float2*)&Arow[(r0+8)*NSEQ + colb + 8]   = w;
            unsigned pa[4];
            pa[0] = pack2(p[0][0], p[0][1]);
            pa[1] = pack2(p[0][2], p[0][3]);
            pa[2] = pack2(p[1][0], p[1][1]);
            pa[3] = pack2(p[1][2], p[1][3]);
#pragma unroll
            for (int njp = 0; njp < 4; njp++) {
                unsigned bv[4];
                ldm_x4t(bv, Vs + SWZ((kg*16 + lrow) * 128 + ((njp*2 + (lane>>4)) * 8) * 2));
                unsigned b0[2] = {bv[0], bv[1]}, b1[2] = {bv[2], bv[3]};
                mma_bf16(Macc[njp*2],     pa, b0);
                mma_bf16(Macc[njp*2 + 1], pa, b1);
            }
        }
        if (kt < 15) { cp_wait<0>(); __syncthreads(); }
    }

    // ---- epilogue: M -> bf16 hi ----
    long mrow0 = qrow + warp * 16 + (lane >> 2);
#pragma unroll
    for (int njv = 0; njv < 8; njv++) {
        int col = hh * HDM + njv * 8 + 2 * (lane & 3);
        bf162 ph;
        ph.x = __float2bfloat16_rn(Macc[njv][0]);
        ph.y = __float2bfloat16_rn(Macc[njv][1]);
        *(bf162*)&Mhg[mrow0 * DDIM + col] = ph;
        ph.x = __float2bfloat16_rn(Macc[njv][2]);
        ph.y = __float2bfloat16_rn(Macc[njv][3]);
        *(bf162*)&Mhg[(mrow0 + 8) * DDIM + col] = ph;
    }
}

// ---------------- elementwise kernels ----------------
__device__ __forceinline__ void split_body(const float* __restrict__ s,
                                           bf16* __restrict__ h, bf16* __restrict__ l,
                                           long i)
{
    float4 v = *(const float4*)(s + i);
    bf16 h0,l0,h1,l1,h2,l2,h3,l3;
    split_bf16(v.x, h0, l0); split_bf16(v.y, h1, l1);
    split_bf16(v.z, h2, l2); split_bf16(v.w, h3, l3);
    bf162 p;
    p.x = h0; p.y = h1; *(bf162*)(h + i)     = p;
    p.x = h2; p.y = h3; *(bf162*)(h + i + 2) = p;
    p.x = l0; p.y = l1; *(bf162*)(l + i)     = p;
    p.x = l2; p.y = l3; *(bf162*)(l + i + 2) = p;
}

__global__ void split_kernel(const float* __restrict__ s, bf16* __restrict__ h, bf16* __restrict__ l)
{
    long i = ((long)blockIdx.x * blockDim.x + threadIdx.x) * 4;
    split_body(s, h, l, i);
}

struct SplitP {
    const float* s[3];
    bf16* h[3]; bf16* l[3];
};
__global__ void split_multi_kernel(SplitP p)
{
    int z = blockIdx.z;
    long i = ((long)blockIdx.x * blockDim.x + threadIdx.x) * 4;
    split_body(p.s[z], p.h[z], p.l[z], i);
}

// VG = V * sigmoid(G) -> bf16 (hi only; PV path is damped)
__global__ void vg_kernel(const float* __restrict__ V, const float* __restrict__ G,
                          bf16* __restrict__ h)
{
    long i = ((long)blockIdx.x * blockDim.x + threadIdx.x) * 4;
    float4 v = *(const float4*)(V + i);
    float4 g = *(const float4*)(G + i);
    bf162 p;
    p.x = __float2bfloat16_rn(v.x * g.x);
    p.y = __float2bfloat16_rn(v.y * g.y);
    *(bf162*)(h + i) = p;
    p.x = __float2bfloat16_rn(v.z * g.z);
    p.y = __float2bfloat16_rn(v.w * g.w);
    *(bf162*)(h + i + 2) = p;
}

// LayerNorm over last dim (1024)
__global__ void ln_kernel(const float* __restrict__ Y,
                          const float* __restrict__ gamma,
                          const float* __restrict__ beta,
                          float* __restrict__ out)
{
    __shared__ float red[256];
    int row = blockIdx.x, tid = threadIdx.x;
    const float4* y4 = (const float4*)(Y + (long)row * DDIM);
    float4 v = y4[tid];

    red[tid] = v.x + v.y + v.z + v.w; __syncthreads();
    for (int o = 128; o > 0; o >>= 1) {
        if (tid < o) red[tid] += red[tid + o];
        __syncthreads();
    }
    float mean = red[0] * (1.f / DDIM);
    __syncthreads();

    float d0 = v.x - mean, d1 = v.y - mean, d2 = v.z - mean, d3 = v.w - mean;
    red[tid] = d0*d0 + d1*d1 + d2*d2 + d3*d3; __syncthreads();
    for (int o = 128; o > 0; o >>= 1) {
        if (tid < o) red[tid] += red[tid + o];
        __syncthreads();
    }
    float var = red[0] * (1.f / DDIM);
    float inv = rsqrtf(var + 1e-5f);

    float4 g  = ((const float4*)gamma)[tid];
    float4 bt = ((const float4*)beta)[tid];
    float4 o4;
    o4.x = g.x * (d0 * inv) + bt.x;
    o4.y = g.y * (d1 * inv) + bt.y;
    o4.z = g.z * (d2 * inv) + bt.z;
    o4.w = g.w * (d3 * inv) + bt.w;
    ((float4*)(out + (long)row * DDIM))[tid] = o4;
}

extern "C" void kernel_launch(void* const* d_in, const int* in_sizes, int n_in,
                              void* d_out, int out_size)
{
    const float* x     = (const float*)d_in[0];
    const float* Wq    = (const float*)d_in[1];
    const float* bq    = (const float*)d_in[2];
    const float* Wk    = (const float*)d_in[3];
    const float* bk    = (const float*)d_in[4];
    const float* Wv    = (const float*)d_in[5];
    const float* bv    = (const float*)d_in[6];
    const float* Wg    = (const float*)d_in[7];
    const float* bg    = (const float*)d_in[8];
    const float* Wp    = (const float*)d_in[9];
    const float* bp    = (const float*)d_in[10];
    const float* gamma = (const float*)d_in[11];
    const float* beta  = (const float*)d_in[12];
    float* outp = (float*)d_out;

    bf16 *xh, *xl, *wh, *wl, *Qh, *Ql, *Kh, *Kl, *VGh, *Mh;
    float *Vf, *Gf, *Y, *Afb;
    cudaGetSymbolAddress((void**)&xh,  g_xh);
    cudaGetSymbolAddress((void**)&xl,  g_xl);
    cudaGetSymbolAddress((void**)&wh,  g_wh);
    cudaGetSymbolAddress((void**)&wl,  g_wl);
    cudaGetSymbolAddress((void**)&Qh,  g_Qh);
    cudaGetSymbolAddress((void**)&Ql,  g_Ql);
    cudaGetSymbolAddress((void**)&Kh,  g_Kh);
    cudaGetSymbolAddress((void**)&Kl,  g_Kl);
    cudaGetSymbolAddress((void**)&Vf,  g_V);
    cudaGetSymbolAddress((void**)&Gf,  g_G);
    cudaGetSymbolAddress((void**)&VGh, g_VGh);
    cudaGetSymbolAddress((void**)&Mh,  g_Mh);
    cudaGetSymbolAddress((void**)&Y,   g_Y);
    cudaGetSymbolAddress((void**)&Afb, g_Afb);

    float* A = ((long)out_size >= OUT1 + AELEMS) ? (outp + OUT1) : Afb;

    const long WSZ = (long)LDIM * DDIM;

    // launches 0-2: splits (x; Wq,Wk; Wv,Wg,Wp)
    split_kernel<<<(BNROWS*(long)LDIM)/1024, 256>>>(x, xh, xl);
    {
        SplitP p;
        p.s[0] = Wq; p.h[0] = wh + 0*WSZ; p.l[0] = wl + 0*WSZ;
        p.s[1] = Wk; p.h[1] = wh + 1*WSZ; p.l[1] = wl + 1*WSZ;
        p.s[2] = Wq; p.h[2] = wh + 0*WSZ; p.l[2] = wl + 0*WSZ; // unused
        dim3 g(WSZ/1024, 1, 2);
        split_multi_kernel<<<g, 256>>>(p);
    }
    {
        SplitP p;
        p.s[0] = Wv; p.h[0] = wh + 2*WSZ; p.l[0] = wl + 2*WSZ;
        p.s[1] = Wg; p.h[1] = wh + 3*WSZ; p.l[1] = wl + 3*WSZ;
        p.s[2] = Wp; p.h[2] = wh + 4*WSZ; p.l[2] = wl + 4*WSZ;
        dim3 g(WSZ/1024, 1, 3);
        split_multi_kernel<<<g, 256>>>(p);
    }

    constexpr int SM_PROJ = 2 * stage_bytes_h(128, 128, 32);
    constexpr int SM_ATTN = 98304;

    cudaFuncSetAttribute(gemm4_kernel<128,128,32,64,32>,
                         cudaFuncAttributeMaxDynamicSharedMemorySize, SM_PROJ);
    cudaFuncSetAttribute(gemm1_kernel<128,128,32,64,32>,
                         cudaFuncAttributeMaxDynamicSharedMemorySize, SM_PROJ);
    cudaFuncSetAttribute(attn_kernel,
                         cudaFuncAttributeMaxDynamicSharedMemorySize, SM_ATTN);

    // launch 3: fused projections
    {
        Ptrs4 p;
        p.Bh[0] = wh + 0*WSZ; p.Bl[0] = wl + 0*WSZ; p.bias[0] = bq;
        p.Cf[0] = nullptr; p.Ch[0] = Qh; p.Cl[0] = Ql; p.act[0] = 0; p.full[0] = 1;
        p.Bh[1] = wh + 1*WSZ; p.Bl[1] = wl + 1*WSZ; p.bias[1] = bk;
        p.Cf[1] = nullptr; p.Ch[1] = Kh; p.Cl[1] = Kl; p.act[1] = 0; p.full[1] = 1;
        p.Bh[2] = wh + 2*WSZ; p.Bl[2] = wl + 2*WSZ; p.bias[2] = bv;
        p.Cf[2] = Vf; p.Ch[2] = nullptr; p.Cl[2] = nullptr; p.act[2] = 0; p.full[2] = 0;
        p.Bh[3] = wh + 3*WSZ; p.Bl[3] = wl + 3*WSZ; p.bias[3] = bg;
        p.Cf[3] = Gf; p.Ch[3] = nullptr; p.Cl[3] = nullptr; p.act[3] = 1; p.full[3] = 0;
        dim3 grid(DDIM/128, BNROWS/128, 4);
        gemm4_kernel<128,128,32,64,32><<<grid, 256, SM_PROJ>>>(
            LDIM, xh, xl, LDIM, DDIM, DDIM, p);
    }

    // launch 4: VG
    vg_kernel<<<(BNROWS*(long)DDIM)/1024, 256>>>(Vf, Gf, VGh);

    // launch 5: two-pass fused attention (ncu -s 5 lands here)
    {
        dim3 grid(NSEQ/128, BDIM*HH);
        attn_kernel<<<grid, 256, SM_ATTN>>>(Qh, Ql, Kh, Kl, VGh, A, Mh);
    }

    // launch 6: Y = x + M @ Wp + bp (hi-only; damped by residual)
    {
        dim3 grid(DDIM/128, BNROWS/128, 1);
        gemm1_kernel<128,128,32,64,32><<<grid, 256, SM_PROJ>>>(
            DDIM, 0,
            Mh, Mh, DDIM,
            wh + 4*WSZ, wl + 4*WSZ, DDIM,
            Y, DDIM, bp, x, DDIM);
    }

    // launch 7: LayerNorm -> out
    ln_kernel<<<BNROWS, 256>>>(Y, gamma, beta, outp);
}

// round 11
// speedup vs baseline: 1.3868x; 1.1182x over previous
#include <cuda_runtime.h>
#include <cuda_bf16.h>
#include <cuda_fp16.h>
#include <math.h>

#define BDIM 2
#define NSEQ 2048
#define LDIM 1024
#define DDIM 1024
#define HH   16
#define HDM  64
#define BNROWS (BDIM*NSEQ)   // 4096
#define SM_SCALE 0.125f

static const long OUT1   = (long)BDIM * NSEQ * DDIM;        // 4,194,304
static const long AELEMS = (long)BDIM * HH * NSEQ * NSEQ;   // 134,217,728

typedef __nv_bfloat16 bf16;
typedef __nv_bfloat162 bf162;
typedef __half fp16;

// ---------------- device scratch (no cudaMalloc anywhere) ----------------
__device__ __align__(256) bf16 g_xh[BNROWS*LDIM], g_xl[BNROWS*LDIM];
__device__ __align__(256) bf16 g_wh[5][LDIM*DDIM], g_wl[5][LDIM*DDIM];
__device__ __align__(256) fp16 g_Q16[BNROWS*DDIM];
__device__ __align__(256) fp16 g_K16[BNROWS*DDIM];
__device__ float g_V[BNROWS*DDIM];
__device__ float g_G[BNROWS*DDIM];
__device__ __align__(256) fp16 g_VG16[BNROWS*DDIM];
__device__ __align__(256) bf16 g_Mh[BNROWS*DDIM];
__device__ float g_Y[BNROWS*DDIM];
__device__ float g_Afb[(size_t)BDIM*HH*NSEQ*NSEQ];  // fallback if A not in output

// ---------------- PTX helpers ----------------
__device__ __forceinline__ unsigned smem_u32(const void* p) {
    return (unsigned)__cvta_generic_to_shared(p);
}
__device__ __forceinline__ void cp16(unsigned dst, const void* src) {
    asm volatile("cp.async.ca.shared.global [%0], [%1], 16;\n" :: "r"(dst), "l"(src));
}
__device__ __forceinline__ void cp_commit() { asm volatile("cp.async.commit_group;\n" ::); }
template<int N> __device__ __forceinline__ void cp_wait() {
    asm volatile("cp.async.wait_group %0;\n" :: "n"(N));
}
__device__ __forceinline__ void ldm_x4(unsigned* d, unsigned addr) {
    asm volatile("ldmatrix.sync.aligned.m8n8.x4.shared.b16 {%0,%1,%2,%3}, [%4];"
                 : "=r"(d[0]), "=r"(d[1]), "=r"(d[2]), "=r"(d[3]) : "r"(addr));
}
__device__ __forceinline__ void ldm_x4t(unsigned* d, unsigned addr) {
    asm volatile("ldmatrix.sync.aligned.m8n8.x4.trans.shared.b16 {%0,%1,%2,%3}, [%4];"
                 : "=r"(d[0]), "=r"(d[1]), "=r"(d[2]), "=r"(d[3]) : "r"(addr));
}
__device__ __forceinline__ void mma_bf16(float* c, const unsigned* a, const unsigned* b) {
    asm volatile(
        "mma.sync.aligned.m16n8k16.row.col.f32.bf16.bf16.f32 "
        "{%0,%1,%2,%3},{%4,%5,%6,%7},{%8,%9},{%0,%1,%2,%3};"
        : "+f"(c[0]), "+f"(c[1]), "+f"(c[2]), "+f"(c[3])
        : "r"(a[0]), "r"(a[1]), "r"(a[2]), "r"(a[3]), "r"(b[0]), "r"(b[1]));
}
__device__ __forceinline__ void mma_fp16(float* c, const unsigned* a, const unsigned* b) {
    asm volatile(
        "mma.sync.aligned.m16n8k16.row.col.f32.f16.f16.f32 "
        "{%0,%1,%2,%3},{%4,%5,%6,%7},{%8,%9},{%0,%1,%2,%3};"
        : "+f"(c[0]), "+f"(c[1]), "+f"(c[2]), "+f"(c[3])
        : "r"(a[0]), "r"(a[1]), "r"(a[2]), "r"(a[3]), "r"(b[0]), "r"(b[1]));
}
__device__ __forceinline__ void split_bf16(float v, bf16& h, bf16& l) {
    h = __float2bfloat16_rn(v);
    l = __float2bfloat16_rn(v - __bfloat162float(h));
}
__device__ __forceinline__ unsigned pack2h(float a, float b) {
    __half2 t = __floats2half2_rn(a, b);
    return *(unsigned*)&t;
}

// SW128 XOR swizzle (byte offsets within a 1024B-aligned 128B-row tile)
#define SWZ(o) ((unsigned)(o) ^ ((((unsigned)(o)) >> 3) & 0x70))

// ---------------------------------------------------------------------------
// GEMM body: bf16 tensor-core GEMM, cp.async 2-stage pipeline, one sync/chunk.
// full=true -> bf16x3 error-compensated. Outputs: fp32 Cf (+bias/act/resid)
// or fp16 C16 (+bias).
// ---------------------------------------------------------------------------
template<int BM, int BN, int BK, int WM, int WN, int THREADS>
__device__ __forceinline__ void gemm_body(
    int K, bool full,
    const bf16* __restrict__ Agh, const bf16* __restrict__ Agl, int lda,
    const bf16* __restrict__ Bgh, const bf16* __restrict__ Bgl, int ldb,
    float* Cf, fp16* C16, int ldc,
    const float* bias, const float* resid, int ldr,
    float alpha, int act)
{
    constexpr int APITCH = BK + 8;
    constexpr int BPITCH = BN + 8;
    constexpr int ABYTES = BM * APITCH * 2;
    constexpr int BBYTES = BK * BPITCH * 2;
    constexpr int STAGE  = 2 * ABYTES + 2 * BBYTES;
    constexpr int MI = WM / 16, NJ = WN / 8;

    extern __shared__ char dsm[];

    const int tid  = threadIdx.x;
    const int lane = tid & 31;
    const int warp = tid >> 5;
    const int wm = warp % (BM/WM);
    const int wn = warp / (BM/WM);
    const int m0 = wm * WM, n0 = wn * WN;
    const int rowBase = blockIdx.y * BM;
    const int colBase = blockIdx.x * BN;
    const int lrow  = lane & 15;
    const int lkoff = (lane >> 4) << 3;

    float acc[MI][NJ][4];
#pragma unroll
    for (int i = 0; i < MI; i++)
#pragma unroll
        for (int j = 0; j < NJ; j++)
#pragma unroll
            for (int q = 0; q < 4; q++) acc[i][j][q] = 0.f;

    auto load_stage = [&](int s, int k0) {
        char* base = dsm + s * STAGE;
        bf16* Ash = (bf16*)(base);
        bf16* Asl = (bf16*)(base + ABYTES);
        bf16* Bsh = (bf16*)(base + 2*ABYTES);
        bf16* Bsl = (bf16*)(base + 2*ABYTES + BBYTES);
        constexpr int ACH = BM * BK / 8;
#pragma unroll
        for (int t = 0; t < ACH; t += THREADS) {
            int idx = t + tid;
            int r = idx / (BK/8);
            int c = (idx % (BK/8)) * 8;
            long so = (long)(rowBase + r) * lda + k0 + c;
            cp16(smem_u32(Ash + r*APITCH + c), Agh + so);
            if (full) cp16(smem_u32(Asl + r*APITCH + c), Agl + so);
        }
        constexpr int BCH = BK * BN / 8;
#pragma unroll
        for (int t = 0; t < BCH; t += THREADS) {
            int idx = t + tid;
            int r = idx / (BN/8);
            int c = (idx % (BN/8)) * 8;
            long so = (long)(k0 + r) * ldb + colBase + c;
            cp16(smem_u32(Bsh + r*BPITCH + c), Bgh + so);
            if (full) cp16(smem_u32(Bsl + r*BPITCH + c), Bgl + so);
        }
    };

    auto compute_stage = [&](int s) {
        char* base = dsm + s * STAGE;
        bf16* Ash = (bf16*)(base);
        bf16* Asl = (bf16*)(base + ABYTES);
        bf16* Bsh = (bf16*)(base + 2*ABYTES);
        bf16* Bsl = (bf16*)(base + 2*ABYTES + BBYTES);
#pragma unroll
        for (int kk = 0; kk < BK; kk += 16) {
            unsigned afh[MI][4], afl[MI][4];
            unsigned bfh[NJ][2], bfl[NJ][2];
#pragma unroll
            for (int mi = 0; mi < MI; mi++) {
                ldm_x4(afh[mi], smem_u32(Ash + (m0 + mi*16 + lrow)*APITCH + kk + lkoff));
                if (full) ldm_x4(afl[mi], smem_u32(Asl + (m0 + mi*16 + lrow)*APITCH + kk + lkoff));
            }
#pragma unroll
            for (int nj = 0; nj < NJ; nj += 2) {
                ldm_x4t(&bfh[nj][0], smem_u32(Bsh + (kk + lrow)*BPITCH + n0 + (nj + (lane>>4))*8));
                if (full) ldm_x4t(&bfl[nj][0], smem_u32(Bsl + (kk + lrow)*BPITCH + n0 + (nj + (lane>>4))*8));
            }
#pragma unroll
            for (int mi = 0; mi < MI; mi++)
#pragma unroll
                for (int nj = 0; nj < NJ; nj++) {
                    mma_bf16(acc[mi][nj], afh[mi], bfh[nj]);
                    if (full) {
                        mma_bf16(acc[mi][nj], afh[mi], bfl[nj]);
                        mma_bf16(acc[mi][nj], afl[mi], bfh[nj]);
                    }
                }
        }
    };

    const int KT = K / BK;
    load_stage(0, 0);
    cp_commit();
    for (int kt = 0; kt < KT; kt++) {
        cp_wait<0>();
        __syncthreads();
        if (kt + 1 < KT) {
            load_stage((kt + 1) & 1, (kt + 1) * BK);
            cp_commit();
        }
        compute_stage(kt & 1);
    }

    // ---- epilogue ----
#pragma unroll
    for (int mi = 0; mi < MI; mi++) {
#pragma unroll
        for (int nj = 0; nj < NJ; nj++) {
            int c = colBase + n0 + nj*8 + 2*(lane & 3);
            float b0 = 0.f, b1 = 0.f;
            if (bias) { b0 = bias[c]; b1 = bias[c+1]; }
#pragma unroll
            for (int half = 0; half < 2; half++) {
                int r = rowBase + m0 + mi*16 + (lane >> 2) + half*8;
                float v0 = acc[mi][nj][half*2+0] * alpha + b0;
                float v1 = acc[mi][nj][half*2+1] * alpha + b1;
                if (act == 1) {
                    v0 = 1.f / (1.f + __expf(-v0));
                    v1 = 1.f / (1.f + __expf(-v1));
                }
                if (resid) {
                    v0 += resid[(long)r * ldr + c];
                    v1 += resid[(long)r * ldr + c + 1];
                }
                long off = (long)r * ldc + c;
                if (Cf) {
                    float2 o; o.x = v0; o.y = v1;
                    *(float2*)&Cf[off] = o;
                }
                if (C16) {
                    __half2 h2 = __floats2half2_rn(v0, v1);
                    *(__half2*)&C16[off] = h2;
                }
            }
        }
    }
}

// multiplexed 4-projection kernel
struct Ptrs4 {
    const bf16* Bh[4]; const bf16* Bl[4];
    const float* bias[4];
    float* Cf[4]; fp16* C16[4];
    int act[4]; int full[4];
};

template<int BM, int BN, int BK, int WM, int WN>
__global__ __launch_bounds__((BM/WM)*(BN/WN)*32, 2)
void gemm4_kernel(int K, const bf16* __restrict__ Ah, const bf16* __restrict__ Al,
                  int lda, int ldb, int ldc, Ptrs4 p)
{
    int z = blockIdx.z;
    gemm_body<BM,BN,BK,WM,WN,(BM/WM)*(BN/WN)*32>(
        K, p.full[z] != 0, Ah, Al, lda, p.Bh[z], p.Bl[z], ldb,
        p.Cf[z], p.C16[z], ldc,
        p.bias[z], nullptr, 0, 1.f, p.act[z]);
}

// single GEMM (out projection)
template<int BM, int BN, int BK, int WM, int WN>
__global__ __launch_bounds__((BM/WM)*(BN/WN)*32, 2)
void gemm1_kernel(int K, int full,
                  const bf16* __restrict__ Ah, const bf16* __restrict__ Al, int lda,
                  const bf16* __restrict__ Bh, const bf16* __restrict__ Bl, int ldb,
                  float* Cf, int ldc,
                  const float* bias, const float* resid, int ldr)
{
    gemm_body<BM,BN,BK,WM,WN,(BM/WM)*(BN/WN)*32>(
        K, full != 0, Ah, Al, lda, Bh, Bl, ldb,
        Cf, nullptr, ldc, bias, resid, ldr, 1.f, 0);
}

constexpr int stage_bytes_h(int BM, int BN, int BK) {
    return 2 * (BM * (BK + 8) * 2) + 2 * (BK * (BN + 8) * 2);
}

// ---------------------------------------------------------------------------
// Two-pass fused attention, all-fp16 operands, hi-only S (err ~1.2e-4 abs):
// pass 1 computes S (8 fp16 mma / 16-key group) -> row sums of exp;
// pass 2 recomputes S bit-identically, writes normalized A (fp32, once),
// and accumulates M += P @ VG in fp16 (damped downstream).
// smem (81920B): Q fp16 [0,16384); stage s at 16384 + s*32768:
//   K +0 (16384), V +16384 (16384). 2 CTAs/SM.
// ---------------------------------------------------------------------------
__global__ __launch_bounds__(256, 2)
void attn_kernel(const fp16* __restrict__ Qg, const fp16* __restrict__ Kg,
                 const fp16* __restrict__ Vg,
                 float* __restrict__ Ag, bf16* __restrict__ Mhg)
{
    extern __shared__ char sm[];
    const unsigned sb = smem_u32(sm);
    const int tid = threadIdx.x, lane = tid & 31, warp = tid >> 5;
    const int bh = blockIdx.y, bb = bh >> 4, hh = bh & 15;
    const int q0 = blockIdx.x * 128;
    const long qrow = (long)bb * NSEQ + q0;
    const fp16* Q = Qg + qrow * DDIM + hh * HDM;
    const fp16* K = Kg + (long)bb * NSEQ * DDIM + hh * HDM;
    const fp16* V = Vg + (long)bb * NSEQ * DDIM + hh * HDM;
    float* Arow = Ag + ((long)bh * NSEQ + q0) * NSEQ;

    const int lrow = lane & 15, lk = (lane >> 4) * 8;

    auto loadQ = [&]() {
        for (int t = tid; t < 1024; t += 256) {
            int r = t >> 3, c = (t & 7) * 8;
            cp16(sb + SWZ(r * 128 + c * 2), Q + (long)r * DDIM + c);
        }
    };
    auto loadK = [&](unsigned dst, int key0) {
        for (int t = tid; t < 1024; t += 256) {
            int r = t >> 3, c = (t & 7) * 8;
            cp16(dst + SWZ(r * 128 + c * 2), K + (long)(key0 + r) * DDIM + c);
        }
    };
    auto loadV = [&](unsigned dst, int key0) {
        for (int t = tid; t < 1024; t += 256) {
            int r = t >> 3, c = (t & 7) * 8;
            cp16(dst + SWZ(r * 128 + c * 2), V + (long)(key0 + r) * DDIM + c);
        }
    };

#define STG(s) (sb + 16384u + (unsigned)(s) * 32768u)

    // ---- prologue: Q + first K tile ----
    loadQ();
    loadK(STG(0), 0);
    cp_commit(); cp_wait<0>(); __syncthreads();

    // preload Q fragments (constant through both passes)
    unsigned aq[4][4];
#pragma unroll
    for (int kk = 0; kk < 4; kk++)
        ldm_x4(aq[kk], sb + SWZ((warp*16 + lrow) * 128 + (kk*16 + lk) * 2));

    // deterministic S for one 16-key group (identical in both passes)
    auto computeS = [&](unsigned kbase, int kg, float (&c)[2][4]) {
#pragma unroll
        for (int kk = 0; kk < 4; kk++) {
            unsigned rh[4];
            ldm_x4(rh, kbase + SWZ((kg*16 + lrow) * 128 + (kk*16 + lk) * 2));
            unsigned b0[2] = {rh[0], rh[2]}, b1[2] = {rh[1], rh[3]};
            mma_fp16(c[0], aq[kk], b0);
            mma_fp16(c[1], aq[kk], b1);
        }
    };

    // ---- pass 1: S -> row sums of exp ----
    float lsum0 = 0.f, lsum1 = 0.f;
    for (int kt = 0; kt < 16; kt++) {
        unsigned cur = STG(kt & 1);
        if (kt < 15) {
            loadK(STG((kt + 1) & 1), (kt + 1) * 128);
            cp_commit();
        }
#pragma unroll 1
        for (int kg = 0; kg < 8; kg++) {
            float c[2][4] = {};
            computeS(cur, kg, c);
            lsum0 += __expf(c[0][0]*SM_SCALE) + __expf(c[0][1]*SM_SCALE)
                   + __expf(c[1][0]*SM_SCALE) + __expf(c[1][1]*SM_SCALE);
            lsum1 += __expf(c[0][2]*SM_SCALE) + __expf(c[0][3]*SM_SCALE)
                   + __expf(c[1][2]*SM_SCALE) + __expf(c[1][3]*SM_SCALE);
        }
        if (kt < 15) { cp_wait<0>(); __syncthreads(); }
    }

    lsum0 += __shfl_xor_sync(0xffffffff, lsum0, 1);
    lsum0 += __shfl_xor_sync(0xffffffff, lsum0, 2);
    lsum1 += __shfl_xor_sync(0xffffffff, lsum1, 1);
    lsum1 += __shfl_xor_sync(0xffffffff, lsum1, 2);
    float invl0 = 1.f / lsum0;
    float invl1 = 1.f / lsum1;

    // ---- pass 2: recompute S, write normalized A, fused PV ----
    __syncthreads();
    loadK(STG(0), 0);
    loadV(STG(0) + 16384, 0);
    cp_commit(); cp_wait<0>(); __syncthreads();

    float Macc[8][4] = {};
    for (int kt = 0; kt < 16; kt++) {
        unsigned stg = STG(kt & 1);
        if (kt < 15) {
            unsigned pre = STG((kt + 1) & 1);
            loadK(pre, (kt + 1) * 128);
            loadV(pre + 16384, (kt + 1) * 128);
            cp_commit();
        }
        unsigned Vs = stg + 16384;
#pragma unroll 1
        for (int kg = 0; kg < 8; kg++) {
            float c[2][4] = {};
            computeS(stg, kg, c);
            float p[2][4];
#pragma unroll
            for (int nj = 0; nj < 2; nj++) {
                p[nj][0] = __expf(c[nj][0] * SM_SCALE) * invl0;
                p[nj][1] = __expf(c[nj][1] * SM_SCALE) * invl0;
                p[nj][2] = __expf(c[nj][2] * SM_SCALE) * invl1;
                p[nj][3] = __expf(c[nj][3] * SM_SCALE) * invl1;
            }
            long colb = (long)kt * 128 + kg * 16 + 2 * (lane & 3);
            long r0 = warp * 16 + (lane >> 2);
            float2 w;
            w.x = p[0][0]; w.y = p[0][1]; *(float2*)&Arow[r0*NSEQ + colb]           = w;
            w.x = p[1][0]; w.y = p[1][1]; *(float2*)&Arow[r0*NSEQ + colb + 8]       = w;
            w.x = p[0][2]; w.y = p[0][3]; *(float2*)&Arow[(r0+8)*NSEQ + colb]       = w;
            w.x = p[1][2]; w.y = p[1][3]; *(float2*)&Arow[(r0+8)*NSEQ + colb + 8]   = w;
            unsigned pa[4];
            pa[0] = pack2h(p[0][0], p[0][1]);
            pa[1] = pack2h(p[0][2], p[0][3]);
            pa[2] = pack2h(p[1][0], p[1][1]);
            pa[3] = pack2h(p[1][2], p[1][3]);
#pragma unroll
            for (int njp = 0; njp < 4; njp++) {
                unsigned bv[4];
                ldm_x4t(bv, Vs + SWZ((kg*16 + lrow) * 128 + ((njp*2 + (lane>>4)) * 8) * 2));
                unsigned b0[2] = {bv[0], bv[1]}, b1[2] = {bv[2], bv[3]};
                mma_fp16(Macc[njp*2],     pa, b0);
                mma_fp16(Macc[njp*2 + 1], pa, b1);
            }
        }
        if (kt < 15) { cp_wait<0>(); __syncthreads(); }
    }

    // ---- epilogue: M -> bf16 hi (for bf16 out-projection) ----
    long mrow0 = qrow + warp * 16 + (lane >> 2);
#pragma unroll
    for (int njv = 0; njv < 8; njv++) {
        int col = hh * HDM + njv * 8 + 2 * (lane & 3);
        bf162 ph;
        ph.x = __float2bfloat16_rn(Macc[njv][0]);
        ph.y = __float2bfloat16_rn(Macc[njv][1]);
        *(bf162*)&Mhg[mrow0 * DDIM + col] = ph;
        ph.x = __float2bfloat16_rn(Macc[njv][2]);
        ph.y = __float2bfloat16_rn(Macc[njv][3]);
        *(bf162*)&Mhg[(mrow0 + 8) * DDIM + col] = ph;
    }
#undef STG
}

// ---------------- elementwise kernels ----------------
__device__ __forceinline__ void split_body(const float* __restrict__ s,
                                           bf16* __restrict__ h, bf16* __restrict__ l,
                                           long i)
{
    float4 v = *(const float4*)(s + i);
    bf16 h0,l0,h1,l1,h2,l2,h3,l3;
    split_bf16(v.x, h0, l0); split_bf16(v.y, h1, l1);
    split_bf16(v.z, h2, l2); split_bf16(v.w, h3, l3);
    bf162 p;
    p.x = h0; p.y = h1; *(bf162*)(h + i)     = p;
    p.x = h2; p.y = h3; *(bf162*)(h + i + 2) = p;
    p.x = l0; p.y = l1; *(bf162*)(l + i)     = p;
    p.x = l2; p.y = l3; *(bf162*)(l + i + 2) = p;
}

__global__ void split_kernel(const float* __restrict__ s, bf16* __restrict__ h, bf16* __restrict__ l)
{
    long i = ((long)blockIdx.x * blockDim.x + threadIdx.x) * 4;
    split_body(s, h, l, i);
}

struct SplitP {
    const float* s[3];
    bf16* h[3]; bf16* l[3];
};
__global__ void split_multi_kernel(SplitP p)
{
    int z = blockIdx.z;
    long i = ((long)blockIdx.x * blockDim.x + threadIdx.x) * 4;
    split_body(p.s[z], p.h[z], p.l[z], i);
}

// VG = V * sigmoid(G) -> fp16
__global__ void vg_kernel(const float* __restrict__ V, const float* __restrict__ G,
                          fp16* __restrict__ h)
{
    long i = ((long)blockIdx.x * blockDim.x + threadIdx.x) * 4;
    float4 v = *(const float4*)(V + i);
    float4 g = *(const float4*)(G + i);
    *(__half2*)(h + i)     = __floats2half2_rn(v.x * g.x, v.y * g.y);
    *(__half2*)(h + i + 2) = __floats2half2_rn(v.z * g.z, v.w * g.w);
}

// LayerNorm over last dim (1024)
__global__ void ln_kernel(const float* __restrict__ Y,
                          const float* __restrict__ gamma,
                          const float* __restrict__ beta,
                          float* __restrict__ out)
{
    __shared__ float red[256];
    int row = blockIdx.x, tid = threadIdx.x;
    const float4* y4 = (const float4*)(Y + (long)row * DDIM);
    float4 v = y4[tid];

    red[tid] = v.x + v.y + v.z + v.w; __syncthreads();
    for (int o = 128; o > 0; o >>= 1) {
        if (tid < o) red[tid] += red[tid + o];
        __syncthreads();
    }
    float mean = red[0] * (1.f / DDIM);
    __syncthreads();

    float d0 = v.x - mean, d1 = v.y - mean, d2 = v.z - mean, d3 = v.w - mean;
    red[tid] = d0*d0 + d1*d1 + d2*d2 + d3*d3; __syncthreads();
    for (int o = 128; o > 0; o >>= 1) {
        if (tid < o) red[tid] += red[tid + o];
        __syncthreads();
    }
    float var = red[0] * (1.f / DDIM);
    float inv = rsqrtf(var + 1e-5f);

    float4 g  = ((const float4*)gamma)[tid];
    float4 bt = ((const float4*)beta)[tid];
    float4 o4;
    o4.x = g.x * (d0 * inv) + bt.x;
    o4.y = g.y * (d1 * inv) + bt.y;
    o4.z = g.z * (d2 * inv) + bt.z;
    o4.w = g.w * (d3 * inv) + bt.w;
    ((float4*)(out + (long)row * DDIM))[tid] = o4;
}

extern "C" void kernel_launch(void* const* d_in, const int* in_sizes, int n_in,
                              void* d_out, int out_size)
{
    const float* x     = (const float*)d_in[0];
    const float* Wq    = (const float*)d_in[1];
    const float* bq    = (const float*)d_in[2];
    const float* Wk    = (const float*)d_in[3];
    const float* bk    = (const float*)d_in[4];
    const float* Wv    = (const float*)d_in[5];
    const float* bv    = (const float*)d_in[6];
    const float* Wg    = (const float*)d_in[7];
    const float* bg    = (const float*)d_in[8];
    const float* Wp    = (const float*)d_in[9];
    const float* bp    = (const float*)d_in[10];
    const float* gamma = (const float*)d_in[11];
    const float* beta  = (const float*)d_in[12];
    float* outp = (float*)d_out;

    bf16 *xh, *xl, *wh, *wl, *Mh;
    fp16 *Q16, *K16, *VG16;
    float *Vf, *Gf, *Y, *Afb;
    cudaGetSymbolAddress((void**)&xh,   g_xh);
    cudaGetSymbolAddress((void**)&xl,   g_xl);
    cudaGetSymbolAddress((void**)&wh,   g_wh);
    cudaGetSymbolAddress((void**)&wl,   g_wl);
    cudaGetSymbolAddress((void**)&Q16,  g_Q16);
    cudaGetSymbolAddress((void**)&K16,  g_K16);
    cudaGetSymbolAddress((void**)&Vf,   g_V);
    cudaGetSymbolAddress((void**)&Gf,   g_G);
    cudaGetSymbolAddress((void**)&VG16, g_VG16);
    cudaGetSymbolAddress((void**)&Mh,   g_Mh);
    cudaGetSymbolAddress((void**)&Y,    g_Y);
    cudaGetSymbolAddress((void**)&Afb,  g_Afb);

    float* A = ((long)out_size >= OUT1 + AELEMS) ? (outp + OUT1) : Afb;

    const long WSZ = (long)LDIM * DDIM;

    // launches 0-2: splits (x; Wq,Wk; Wv,Wg,Wp)
    split_kernel<<<(BNROWS*(long)LDIM)/1024, 256>>>(x, xh, xl);
    {
        SplitP p;
        p.s[0] = Wq; p.h[0] = wh + 0*WSZ; p.l[0] = wl + 0*WSZ;
        p.s[1] = Wk; p.h[1] = wh + 1*WSZ; p.l[1] = wl + 1*WSZ;
        p.s[2] = Wq; p.h[2] = wh + 0*WSZ; p.l[2] = wl + 0*WSZ; // unused
        dim3 g(WSZ/1024, 1, 2);
        split_multi_kernel<<<g, 256>>>(p);
    }
    {
        SplitP p;
        p.s[0] = Wv; p.h[0] = wh + 2*WSZ; p.l[0] = wl + 2*WSZ;
        p.s[1] = Wg; p.h[1] = wh + 3*WSZ; p.l[1] = wl + 3*WSZ;
        p.s[2] = Wp; p.h[2] = wh + 4*WSZ; p.l[2] = wl + 4*WSZ;
        dim3 g(WSZ/1024, 1, 3);
        split_multi_kernel<<<g, 256>>>(p);
    }

    constexpr int SM_PROJ = 2 * stage_bytes_h(128, 128, 32);
    constexpr int SM_ATTN = 81920;

    cudaFuncSetAttribute(gemm4_kernel<128,128,32,64,32>,
                         cudaFuncAttributeMaxDynamicSharedMemorySize, SM_PROJ);
    cudaFuncSetAttribute(gemm1_kernel<128,128,32,64,32>,
                         cudaFuncAttributeMaxDynamicSharedMemorySize, SM_PROJ);
    cudaFuncSetAttribute(attn_kernel,
                         cudaFuncAttributeMaxDynamicSharedMemorySize, SM_ATTN);

    // launch 3: fused projections (Q,K -> fp16 via bf16x3; V,G -> f32 hi-only)
    {
        Ptrs4 p;
        p.Bh[0] = wh + 0*WSZ; p.Bl[0] = wl + 0*WSZ; p.bias[0] = bq;
        p.Cf[0] = nullptr; p.C16[0] = Q16; p.act[0] = 0; p.full[0] = 1;
        p.Bh[1] = wh + 1*WSZ; p.Bl[1] = wl + 1*WSZ; p.bias[1] = bk;
        p.Cf[1] = nullptr; p.C16[1] = K16; p.act[1] = 0; p.full[1] = 1;
        p.Bh[2] = wh + 2*WSZ; p.Bl[2] = wl + 2*WSZ; p.bias[2] = bv;
        p.Cf[2] = Vf; p.C16[2] = nullptr; p.act[2] = 0; p.full[2] = 0;
        p.Bh[3] = wh + 3*WSZ; p.Bl[3] = wl + 3*WSZ; p.bias[3] = bg;
        p.Cf[3] = Gf; p.C16[3] = nullptr; p.act[3] = 1; p.full[3] = 0;
        dim3 grid(DDIM/128, BNROWS/128, 4);
        gemm4_kernel<128,128,32,64,32><<<grid, 256, SM_PROJ>>>(
            LDIM, xh, xl, LDIM, DDIM, DDIM, p);
    }

    // launch 4: VG -> fp16
    vg_kernel<<<(BNROWS*(long)DDIM)/1024, 256>>>(Vf, Gf, VG16);

    // launch 5: two-pass fp16 attention (ncu -s 5 lands here)
    {
        dim3 grid(NSEQ/128, BDIM*HH);
        attn_kernel<<<grid, 256, SM_ATTN>>>(Q16, K16, VG16, A, Mh);
    }

    // launch 6: Y = x + M @ Wp + bp (bf16 hi-only; damped by residual)
    {
        dim3 grid(DDIM/128, BNROWS/128, 1);
        gemm1_kernel<128,128,32,64,32><<<grid, 256, SM_PROJ>>>(
            DDIM, 0,
            Mh, Mh, DDIM,
            wh + 4*WSZ, wl + 4*WSZ, DDIM,
            Y, DDIM, bp, x, DDIM);
    }

    // launch 7: LayerNorm -> out
    ln_kernel<<<BNROWS, 256>>>(Y, gamma, beta, outp);
}

// round 12
// speedup vs baseline: 1.9431x; 1.4012x over previous
#include <cuda_runtime.h>
#include <cuda_fp16.h>
#include <math.h>

#define BDIM 2
#define NSEQ 2048
#define LDIM 1024
#define DDIM 1024
#define HH   16
#define HDM  64
#define BNROWS (BDIM*NSEQ)   // 4096
#define SM_SCALE 0.125f

static const long OUT1   = (long)BDIM * NSEQ * DDIM;        // 4,194,304
static const long AELEMS = (long)BDIM * HH * NSEQ * NSEQ;   // 134,217,728

typedef __half fp16;

// ---------------- device scratch (no cudaMalloc anywhere) ----------------
__device__ __align__(256) fp16 g_x16[BNROWS*LDIM];
__device__ __align__(256) fp16 g_w16[5][LDIM*DDIM];
__device__ __align__(256) fp16 g_Q16[BNROWS*DDIM];
__device__ __align__(256) fp16 g_K16[BNROWS*DDIM];
__device__ __align__(256) fp16 g_V16[BNROWS*DDIM];
__device__ __align__(256) fp16 g_G16[BNROWS*DDIM];
__device__ __align__(256) fp16 g_VG16[BNROWS*DDIM];
__device__ __align__(256) fp16 g_M16[BNROWS*DDIM];
__device__ float g_Y[BNROWS*DDIM];
__device__ float g_Afb[(size_t)BDIM*HH*NSEQ*NSEQ];  // fallback if A not in output

// ---------------- PTX helpers ----------------
__device__ __forceinline__ unsigned smem_u32(const void* p) {
    return (unsigned)__cvta_generic_to_shared(p);
}
__device__ __forceinline__ void cp16(unsigned dst, const void* src) {
    asm volatile("cp.async.ca.shared.global [%0], [%1], 16;\n" :: "r"(dst), "l"(src));
}
__device__ __forceinline__ void cp_commit() { asm volatile("cp.async.commit_group;\n" ::); }
template<int N> __device__ __forceinline__ void cp_wait() {
    asm volatile("cp.async.wait_group %0;\n" :: "n"(N));
}
__device__ __forceinline__ void ldm_x4(unsigned* d, unsigned addr) {
    asm volatile("ldmatrix.sync.aligned.m8n8.x4.shared.b16 {%0,%1,%2,%3}, [%4];"
                 : "=r"(d[0]), "=r"(d[1]), "=r"(d[2]), "=r"(d[3]) : "r"(addr));
}
__device__ __forceinline__ void ldm_x4t(unsigned* d, unsigned addr) {
    asm volatile("ldmatrix.sync.aligned.m8n8.x4.trans.shared.b16 {%0,%1,%2,%3}, [%4];"
                 : "=r"(d[0]), "=r"(d[1]), "=r"(d[2]), "=r"(d[3]) : "r"(addr));
}
__device__ __forceinline__ void mma_fp16(float* c, const unsigned* a, const unsigned* b) {
    asm volatile(
        "mma.sync.aligned.m16n8k16.row.col.f32.f16.f16.f32 "
        "{%0,%1,%2,%3},{%4,%5,%6,%7},{%8,%9},{%0,%1,%2,%3};"
        : "+f"(c[0]), "+f"(c[1]), "+f"(c[2]), "+f"(c[3])
        : "r"(a[0]), "r"(a[1]), "r"(a[2]), "r"(a[3]), "r"(b[0]), "r"(b[1]));
}
__device__ __forceinline__ unsigned pack2h(float a, float b) {
    __half2 t = __floats2half2_rn(a, b);
    return *(unsigned*)&t;
}

// SW128 XOR swizzle (byte offsets within a 1024B-aligned 128B-row tile)
#define SWZ(o) ((unsigned)(o) ^ ((((unsigned)(o)) >> 3) & 0x70))

// ---------------------------------------------------------------------------
// GEMM body: fp16 hi-only tensor-core GEMM, cp.async 2-stage, one sync/chunk.
// A: [M,K] fp16 row-major. B: [K,N] fp16 row-major (NN).
// Outputs: fp16 C16 (+bias, optional sigmoid) and/or fp32 Cf (+bias+resid).
// ---------------------------------------------------------------------------
template<int BM, int BN, int BK, int WM, int WN, int THREADS>
__device__ __forceinline__ void gemm_body(
    int K,
    const fp16* __restrict__ Ag, int lda,
    const fp16* __restrict__ Bg, int ldb,
    float* Cf, fp16* C16, int ldc,
    const float* bias, const float* resid, int ldr, int act)
{
    constexpr int APITCH = BK + 8;
    constexpr int BPITCH = BN + 8;
    constexpr int ABYTES = BM * APITCH * 2;
    constexpr int BBYTES = BK * BPITCH * 2;
    constexpr int STAGE  = ABYTES + BBYTES;
    constexpr int MI = WM / 16, NJ = WN / 8;

    extern __shared__ char dsm[];

    const int tid  = threadIdx.x;
    const int lane = tid & 31;
    const int warp = tid >> 5;
    const int wm = warp % (BM/WM);
    const int wn = warp / (BM/WM);
    const int m0 = wm * WM, n0 = wn * WN;
    const int rowBase = blockIdx.y * BM;
    const int colBase = blockIdx.x * BN;
    const int lrow  = lane & 15;
    const int lkoff = (lane >> 4) << 3;

    float acc[MI][NJ][4];
#pragma unroll
    for (int i = 0; i < MI; i++)
#pragma unroll
        for (int j = 0; j < NJ; j++)
#pragma unroll
            for (int q = 0; q < 4; q++) acc[i][j][q] = 0.f;

    auto load_stage = [&](int s, int k0) {
        char* base = dsm + s * STAGE;
        fp16* As = (fp16*)(base);
        fp16* Bs = (fp16*)(base + ABYTES);
        constexpr int ACH = BM * BK / 8;
#pragma unroll
        for (int t = 0; t < ACH; t += THREADS) {
            int idx = t + tid;
            int r = idx / (BK/8);
            int c = (idx % (BK/8)) * 8;
            cp16(smem_u32(As + r*APITCH + c), Ag + (long)(rowBase + r) * lda + k0 + c);
        }
        constexpr int BCH = BK * BN / 8;
#pragma unroll
        for (int t = 0; t < BCH; t += THREADS) {
            int idx = t + tid;
            int r = idx / (BN/8);
            int c = (idx % (BN/8)) * 8;
            cp16(smem_u32(Bs + r*BPITCH + c), Bg + (long)(k0 + r) * ldb + colBase + c);
        }
    };

    auto compute_stage = [&](int s) {
        char* base = dsm + s * STAGE;
        fp16* As = (fp16*)(base);
        fp16* Bs = (fp16*)(base + ABYTES);
#pragma unroll
        for (int kk = 0; kk < BK; kk += 16) {
            unsigned af[MI][4];
            unsigned bf[NJ][2];
#pragma unroll
            for (int mi = 0; mi < MI; mi++)
                ldm_x4(af[mi], smem_u32(As + (m0 + mi*16 + lrow)*APITCH + kk + lkoff));
#pragma unroll
            for (int nj = 0; nj < NJ; nj += 2)
                ldm_x4t(&bf[nj][0], smem_u32(Bs + (kk + lrow)*BPITCH + n0 + (nj + (lane>>4))*8));
#pragma unroll
            for (int mi = 0; mi < MI; mi++)
#pragma unroll
                for (int nj = 0; nj < NJ; nj++)
                    mma_fp16(acc[mi][nj], af[mi], bf[nj]);
        }
    };

    const int KT = K / BK;
    load_stage(0, 0);
    cp_commit();
    for (int kt = 0; kt < KT; kt++) {
        cp_wait<0>();
        __syncthreads();
        if (kt + 1 < KT) {
            load_stage((kt + 1) & 1, (kt + 1) * BK);
            cp_commit();
        }
        compute_stage(kt & 1);
    }

    // ---- epilogue ----
#pragma unroll
    for (int mi = 0; mi < MI; mi++) {
#pragma unroll
        for (int nj = 0; nj < NJ; nj++) {
            int c = colBase + n0 + nj*8 + 2*(lane & 3);
            float b0 = 0.f, b1 = 0.f;
            if (bias) { b0 = bias[c]; b1 = bias[c+1]; }
#pragma unroll
            for (int half = 0; half < 2; half++) {
                int r = rowBase + m0 + mi*16 + (lane >> 2) + half*8;
                float v0 = acc[mi][nj][half*2+0] + b0;
                float v1 = acc[mi][nj][half*2+1] + b1;
                if (act == 1) {
                    v0 = 1.f / (1.f + __expf(-v0));
                    v1 = 1.f / (1.f + __expf(-v1));
                }
                if (resid) {
                    v0 += resid[(long)r * ldr + c];
                    v1 += resid[(long)r * ldr + c + 1];
                }
                long off = (long)r * ldc + c;
                if (Cf) {
                    float2 o; o.x = v0; o.y = v1;
                    *(float2*)&Cf[off] = o;
                }
                if (C16) {
                    *(__half2*)&C16[off] = __floats2half2_rn(v0, v1);
                }
            }
        }
    }
}

// multiplexed 4-projection kernel (all-fp16)
struct Ptrs4 {
    const fp16* B16[4];
    const float* bias[4];
    fp16* C16[4];
    int act[4];
};

template<int BM, int BN, int BK, int WM, int WN>
__global__ __launch_bounds__((BM/WM)*(BN/WN)*32, 2)
void gemm4_kernel(int K, const fp16* __restrict__ A16,
                  int lda, int ldb, int ldc, Ptrs4 p)
{
    int z = blockIdx.z;
    gemm_body<BM,BN,BK,WM,WN,(BM/WM)*(BN/WN)*32>(
        K, A16, lda, p.B16[z], ldb,
        nullptr, p.C16[z], ldc, p.bias[z], nullptr, 0, p.act[z]);
}

// single GEMM (out projection): fp32 output + bias + residual
template<int BM, int BN, int BK, int WM, int WN>
__global__ __launch_bounds__((BM/WM)*(BN/WN)*32, 2)
void gemm1_kernel(int K,
                  const fp16* __restrict__ A16, int lda,
                  const fp16* __restrict__ B16, int ldb,
                  float* Cf, int ldc,
                  const float* bias, const float* resid, int ldr)
{
    gemm_body<BM,BN,BK,WM,WN,(BM/WM)*(BN/WN)*32>(
        K, A16, lda, B16, ldb,
        Cf, nullptr, ldc, bias, resid, ldr, 0);
}

constexpr int stage_bytes_h(int BM, int BN, int BK) {
    return (BM * (BK + 8) * 2) + (BK * (BN + 8) * 2);
}

// ---------------------------------------------------------------------------
// Two-pass fused attention, all-fp16 (unchanged from round 11 winner except
// M output is fp16 now).
// smem (81920B): Q fp16 [0,16384); stage s at 16384 + s*32768:
//   K +0 (16384), V +16384 (16384). 2 CTAs/SM.
// ---------------------------------------------------------------------------
__global__ __launch_bounds__(256, 2)
void attn_kernel(const fp16* __restrict__ Qg, const fp16* __restrict__ Kg,
                 const fp16* __restrict__ Vg,
                 float* __restrict__ Ag, fp16* __restrict__ Mg)
{
    extern __shared__ char sm[];
    const unsigned sb = smem_u32(sm);
    const int tid = threadIdx.x, lane = tid & 31, warp = tid >> 5;
    const int bh = blockIdx.y, bb = bh >> 4, hh = bh & 15;
    const int q0 = blockIdx.x * 128;
    const long qrow = (long)bb * NSEQ + q0;
    const fp16* Q = Qg + qrow * DDIM + hh * HDM;
    const fp16* K = Kg + (long)bb * NSEQ * DDIM + hh * HDM;
    const fp16* V = Vg + (long)bb * NSEQ * DDIM + hh * HDM;
    float* Arow = Ag + ((long)bh * NSEQ + q0) * NSEQ;

    const int lrow = lane & 15, lk = (lane >> 4) * 8;

    auto loadQ = [&]() {
        for (int t = tid; t < 1024; t += 256) {
            int r = t >> 3, c = (t & 7) * 8;
            cp16(sb + SWZ(r * 128 + c * 2), Q + (long)r * DDIM + c);
        }
    };
    auto loadK = [&](unsigned dst, int key0) {
        for (int t = tid; t < 1024; t += 256) {
            int r = t >> 3, c = (t & 7) * 8;
            cp16(dst + SWZ(r * 128 + c * 2), K + (long)(key0 + r) * DDIM + c);
        }
    };
    auto loadV = [&](unsigned dst, int key0) {
        for (int t = tid; t < 1024; t += 256) {
            int r = t >> 3, c = (t & 7) * 8;
            cp16(dst + SWZ(r * 128 + c * 2), V + (long)(key0 + r) * DDIM + c);
        }
    };

#define STG(s) (sb + 16384u + (unsigned)(s) * 32768u)

    loadQ();
    loadK(STG(0), 0);
    cp_commit(); cp_wait<0>(); __syncthreads();

    unsigned aq[4][4];
#pragma unroll
    for (int kk = 0; kk < 4; kk++)
        ldm_x4(aq[kk], sb + SWZ((warp*16 + lrow) * 128 + (kk*16 + lk) * 2));

    auto computeS = [&](unsigned kbase, int kg, float (&c)[2][4]) {
#pragma unroll
        for (int kk = 0; kk < 4; kk++) {
            unsigned rh[4];
            ldm_x4(rh, kbase + SWZ((kg*16 + lrow) * 128 + (kk*16 + lk) * 2));
            unsigned b0[2] = {rh[0], rh[2]}, b1[2] = {rh[1], rh[3]};
            mma_fp16(c[0], aq[kk], b0);
            mma_fp16(c[1], aq[kk], b1);
        }
    };

    // ---- pass 1: S -> row sums of exp ----
    float lsum0 = 0.f, lsum1 = 0.f;
    for (int kt = 0; kt < 16; kt++) {
        unsigned cur = STG(kt & 1);
        if (kt < 15) {
            loadK(STG((kt + 1) & 1), (kt + 1) * 128);
            cp_commit();
        }
#pragma unroll 1
        for (int kg = 0; kg < 8; kg++) {
            float c[2][4] = {};
            computeS(cur, kg, c);
            lsum0 += __expf(c[0][0]*SM_SCALE) + __expf(c[0][1]*SM_SCALE)
                   + __expf(c[1][0]*SM_SCALE) + __expf(c[1][1]*SM_SCALE);
            lsum1 += __expf(c[0][2]*SM_SCALE) + __expf(c[0][3]*SM_SCALE)
                   + __expf(c[1][2]*SM_SCALE) + __expf(c[1][3]*SM_SCALE);
        }
        if (kt < 15) { cp_wait<0>(); __syncthreads(); }
    }

    lsum0 += __shfl_xor_sync(0xffffffff, lsum0, 1);
    lsum0 += __shfl_xor_sync(0xffffffff, lsum0, 2);
    lsum1 += __shfl_xor_sync(0xffffffff, lsum1, 1);
    lsum1 += __shfl_xor_sync(0xffffffff, lsum1, 2);
    float invl0 = 1.f / lsum0;
    float invl1 = 1.f / lsum1;

    // ---- pass 2: recompute S, write normalized A, fused PV ----
    __syncthreads();
    loadK(STG(0), 0);
    loadV(STG(0) + 16384, 0);
    cp_commit(); cp_wait<0>(); __syncthreads();

    float Macc[8][4] = {};
    for (int kt = 0; kt < 16; kt++) {
        unsigned stg = STG(kt & 1);
        if (kt < 15) {
            unsigned pre = STG((kt + 1) & 1);
            loadK(pre, (kt + 1) * 128);
            loadV(pre + 16384, (kt + 1) * 128);
            cp_commit();
        }
        unsigned Vs = stg + 16384;
#pragma unroll 1
        for (int kg = 0; kg < 8; kg++) {
            float c[2][4] = {};
            computeS(stg, kg, c);
            float p[2][4];
#pragma unroll
            for (int nj = 0; nj < 2; nj++) {
                p[nj][0] = __expf(c[nj][0] * SM_SCALE) * invl0;
                p[nj][1] = __expf(c[nj][1] * SM_SCALE) * invl0;
                p[nj][2] = __expf(c[nj][2] * SM_SCALE) * invl1;
                p[nj][3] = __expf(c[nj][3] * SM_SCALE) * invl1;
            }
            long colb = (long)kt * 128 + kg * 16 + 2 * (lane & 3);
            long r0 = warp * 16 + (lane >> 2);
            float2 w;
            w.x = p[0][0]; w.y = p[0][1]; *(float2*)&Arow[r0*NSEQ + colb]           = w;
            w.x = p[1][0]; w.y = p[1][1]; *(float2*)&Arow[r0*NSEQ + colb + 8]       = w;
            w.x = p[0][2]; w.y = p[0][3]; *(float2*)&Arow[(r0+8)*NSEQ + colb]       = w;
            w.x = p[1][2]; w.y = p[1][3]; *(float2*)&Arow[(r0+8)*NSEQ + colb + 8]   = w;
            unsigned pa[4];
            pa[0] = pack2h(p[0][0], p[0][1]);
            pa[1] = pack2h(p[0][2], p[0][3]);
            pa[2] = pack2h(p[1][0], p[1][1]);
            pa[3] = pack2h(p[1][2], p[1][3]);
#pragma unroll
            for (int njp = 0; njp < 4; njp++) {
                unsigned bv[4];
                ldm_x4t(bv, Vs + SWZ((kg*16 + lrow) * 128 + ((njp*2 + (lane>>4)) * 8) * 2));
                unsigned b0[2] = {bv[0], bv[1]}, b1[2] = {bv[2], bv[3]};
                mma_fp16(Macc[njp*2],     pa, b0);
                mma_fp16(Macc[njp*2 + 1], pa, b1);
            }
        }
        if (kt < 15) { cp_wait<0>(); __syncthreads(); }
    }

    // ---- epilogue: M -> fp16 ----
    long mrow0 = qrow + warp * 16 + (lane >> 2);
#pragma unroll
    for (int njv = 0; njv < 8; njv++) {
        int col = hh * HDM + njv * 8 + 2 * (lane & 3);
        *(__half2*)&Mg[mrow0 * DDIM + col] =
            __floats2half2_rn(Macc[njv][0], Macc[njv][1]);
        *(__half2*)&Mg[(mrow0 + 8) * DDIM + col] =
            __floats2half2_rn(Macc[njv][2], Macc[njv][3]);
    }
#undef STG
}

// ---------------- elementwise kernels ----------------
__device__ __forceinline__ void conv_body(const float* __restrict__ s,
                                          fp16* __restrict__ d, long i)
{
    float4 v = *(const float4*)(s + i);
    *(__half2*)(d + i)     = __floats2half2_rn(v.x, v.y);
    *(__half2*)(d + i + 2) = __floats2half2_rn(v.z, v.w);
}

__global__ void conv_kernel(const float* __restrict__ s, fp16* __restrict__ d)
{
    long i = ((long)blockIdx.x * blockDim.x + threadIdx.x) * 4;
    conv_body(s, d, i);
}

struct ConvP { const float* s[3]; fp16* d[3]; };
__global__ void conv_multi_kernel(ConvP p)
{
    int z = blockIdx.z;
    long i = ((long)blockIdx.x * blockDim.x + threadIdx.x) * 4;
    conv_body(p.s[z], p.d[z], i);
}

// VG = V16 * G16 (G already post-sigmoid) -> fp16
__global__ void vg_kernel(const fp16* __restrict__ V, const fp16* __restrict__ G,
                          fp16* __restrict__ h)
{
    long i = ((long)blockIdx.x * blockDim.x + threadIdx.x) * 8;
    float4 v = *(const float4*)(V + i);   // 8 halves
    float4 g = *(const float4*)(G + i);
    __half2* vp = (__half2*)&v;
    __half2* gp = (__half2*)&g;
    float4 o;
    __half2* op = (__half2*)&o;
#pragma unroll
    for (int j = 0; j < 4; j++) op[j] = __hmul2(vp[j], gp[j]);
    *(float4*)(h + i) = o;
}

// LayerNorm over last dim (1024)
__global__ void ln_kernel(const float* __restrict__ Y,
                          const float* __restrict__ gamma,
                          const float* __restrict__ beta,
                          float* __restrict__ out)
{
    __shared__ float red[256];
    int row = blockIdx.x, tid = threadIdx.x;
    const float4* y4 = (const float4*)(Y + (long)row * DDIM);
    float4 v = y4[tid];

    red[tid] = v.x + v.y + v.z + v.w; __syncthreads();
    for (int o = 128; o > 0; o >>= 1) {
        if (tid < o) red[tid] += red[tid + o];
        __syncthreads();
    }
    float mean = red[0] * (1.f / DDIM);
    __syncthreads();

    float d0 = v.x - mean, d1 = v.y - mean, d2 = v.z - mean, d3 = v.w - mean;
    red[tid] = d0*d0 + d1*d1 + d2*d2 + d3*d3; __syncthreads();
    for (int o = 128; o > 0; o >>= 1) {
        if (tid < o) red[tid] += red[tid + o];
        __syncthreads();
    }
    float var = red[0] * (1.f / DDIM);
    float inv = rsqrtf(var + 1e-5f);

    float4 g  = ((const float4*)gamma)[tid];
    float4 bt = ((const float4*)beta)[tid];
    float4 o4;
    o4.x = g.x * (d0 * inv) + bt.x;
    o4.y = g.y * (d1 * inv) + bt.y;
    o4.z = g.z * (d2 * inv) + bt.z;
    o4.w = g.w * (d3 * inv) + bt.w;
    ((float4*)(out + (long)row * DDIM))[tid] = o4;
}

extern "C" void kernel_launch(void* const* d_in, const int* in_sizes, int n_in,
                              void* d_out, int out_size)
{
    const float* x     = (const float*)d_in[0];
    const float* Wq    = (const float*)d_in[1];
    const float* bq    = (const float*)d_in[2];
    const float* Wk    = (const float*)d_in[3];
    const float* bk    = (const float*)d_in[4];
    const float* Wv    = (const float*)d_in[5];
    const float* bv    = (const float*)d_in[6];
    const float* Wg    = (const float*)d_in[7];
    const float* bg    = (const float*)d_in[8];
    const float* Wp    = (const float*)d_in[9];
    const float* bp    = (const float*)d_in[10];
    const float* gamma = (const float*)d_in[11];
    const float* beta  = (const float*)d_in[12];
    float* outp = (float*)d_out;

    fp16 *x16, *w16, *Q16, *K16, *V16, *G16, *VG16, *M16;
    float *Y, *Afb;
    cudaGetSymbolAddress((void**)&x16,  g_x16);
    cudaGetSymbolAddress((void**)&w16,  g_w16);
    cudaGetSymbolAddress((void**)&Q16,  g_Q16);
    cudaGetSymbolAddress((void**)&K16,  g_K16);
    cudaGetSymbolAddress((void**)&V16,  g_V16);
    cudaGetSymbolAddress((void**)&G16,  g_G16);
    cudaGetSymbolAddress((void**)&VG16, g_VG16);
    cudaGetSymbolAddress((void**)&M16,  g_M16);
    cudaGetSymbolAddress((void**)&Y,    g_Y);
    cudaGetSymbolAddress((void**)&Afb,  g_Afb);

    float* A = ((long)out_size >= OUT1 + AELEMS) ? (outp + OUT1) : Afb;

    const long WSZ = (long)LDIM * DDIM;

    // launches 0-2: fp32 -> fp16 converts (x; Wq,Wk; Wv,Wg,Wp)
    conv_kernel<<<(BNROWS*(long)LDIM)/1024, 256>>>(x, x16);
    {
        ConvP p;
        p.s[0] = Wq; p.d[0] = w16 + 0*WSZ;
        p.s[1] = Wk; p.d[1] = w16 + 1*WSZ;
        p.s[2] = Wq; p.d[2] = w16 + 0*WSZ;  // unused
        dim3 g(WSZ/1024, 1, 2);
        conv_multi_kernel<<<g, 256>>>(p);
    }
    {
        ConvP p;
        p.s[0] = Wv; p.d[0] = w16 + 2*WSZ;
        p.s[1] = Wg; p.d[1] = w16 + 3*WSZ;
        p.s[2] = Wp; p.d[2] = w16 + 4*WSZ;
        dim3 g(WSZ/1024, 1, 3);
        conv_multi_kernel<<<g, 256>>>(p);
    }

    constexpr int SM_PROJ = 2 * stage_bytes_h(128, 128, 32);   // 37888
    constexpr int SM_ATTN = 81920;

    cudaFuncSetAttribute(gemm4_kernel<128,128,32,64,32>,
                         cudaFuncAttributeMaxDynamicSharedMemorySize, SM_PROJ);
    cudaFuncSetAttribute(gemm1_kernel<128,128,32,64,32>,
                         cudaFuncAttributeMaxDynamicSharedMemorySize, SM_PROJ);
    cudaFuncSetAttribute(attn_kernel,
                         cudaFuncAttributeMaxDynamicSharedMemorySize, SM_ATTN);

    // launch 3: fused fp16 projections (Q, K, V, sigmoid-G)
    {
        Ptrs4 p;
        p.B16[0] = w16 + 0*WSZ; p.bias[0] = bq; p.C16[0] = Q16; p.act[0] = 0;
        p.B16[1] = w16 + 1*WSZ; p.bias[1] = bk; p.C16[1] = K16; p.act[1] = 0;
        p.B16[2] = w16 + 2*WSZ; p.bias[2] = bv; p.C16[2] = V16; p.act[2] = 0;
        p.B16[3] = w16 + 3*WSZ; p.bias[3] = bg; p.C16[3] = G16; p.act[3] = 1;
        dim3 grid(DDIM/128, BNROWS/128, 4);
        gemm4_kernel<128,128,32,64,32><<<grid, 256, SM_PROJ>>>(
            LDIM, x16, LDIM, DDIM, DDIM, p);
    }

    // launch 4: VG = V * G
    vg_kernel<<<(BNROWS*(long)DDIM)/2048, 256>>>(V16, G16, VG16);

    // launch 5: two-pass fp16 attention (ncu -s 5 lands here)
    {
        dim3 grid(NSEQ/128, BDIM*HH);
        attn_kernel<<<grid, 256, SM_ATTN>>>(Q16, K16, VG16, A, M16);
    }

    // launch 6: Y = x + M @ Wp + bp
    {
        dim3 grid(DDIM/128, BNROWS/128, 1);
        gemm1_kernel<128,128,32,64,32><<<grid, 256, SM_PROJ>>>(
            DDIM, M16, DDIM, w16 + 4*WSZ, DDIM,
            Y, DDIM, bp, x, DDIM);
    }

    // launch 7: LayerNorm -> out
    ln_kernel<<<BNROWS, 256>>>(Y, gamma, beta, outp);
}